// round 1
// baseline (speedup 1.0000x reference)
#include <cuda_runtime.h>
#include <math.h>

// ---------------- problem constants ----------------
#define T_TOK   8192          // B*S
#define D_DIM   1024
#define E_EXP   8
#define TOPK    2
#define FF_DIM  2048
#define EFF     (E_EXP * FF_DIM)   // 16384, row stride of w1
#define NROWS   (T_TOK * TOPK)     // 16384 gathered rows total

// ---------------- device scratch (static: no allocations allowed) ----------------
__device__ float g_h[(size_t)NROWS * FF_DIM];       // 134 MB: gelu(x @ w1_e) rows
__device__ float g_contrib[(size_t)NROWS * D_DIM];  // 67 MB: per-(token,expert) h @ w2_e
__device__ int   g_cnt[E_EXP];
__device__ int   g_base[E_EXP];
__device__ int   g_cursor[E_EXP];
__device__ int   g_rowtok[NROWS];
__device__ float g_roww[NROWS];
__device__ int   g_rowloc[NROWS];   // token*2+k -> gathered row position
__device__ int   g_sel[NROWS];      // token*2+k -> expert id
__device__ float g_wsel[NROWS];     // token*2+k -> normalized weight
__device__ float g_zsum;
__device__ float g_psum[E_EXP];

// ---------------- init ----------------
__global__ void init_kernel() {
    int i = threadIdx.x;
    if (i < E_EXP) { g_cnt[i] = 0; g_psum[i] = 0.f; }
    if (i == 0)    { g_zsum = 0.f; }
}

// ---------------- router: logits, softmax, top-2, loss accumulation ----------------
__global__ void router_kernel(const float* __restrict__ x,
                              const float* __restrict__ rw) {
    __shared__ float sx[D_DIM];
    __shared__ float slog[E_EXP];
    int t = blockIdx.x;
    const float* xr = x + (size_t)t * D_DIM;
    for (int i = threadIdx.x; i < D_DIM; i += blockDim.x) sx[i] = xr[i];
    __syncthreads();

    int w = threadIdx.x >> 5, lane = threadIdx.x & 31;
    // 8 warps, one expert per warp
    float acc = 0.f;
    const float* we = rw + w * D_DIM;
    for (int i = lane; i < D_DIM; i += 32) acc += sx[i] * we[i];
    #pragma unroll
    for (int o = 16; o; o >>= 1) acc += __shfl_xor_sync(0xffffffffu, acc, o);
    if (lane == 0) slog[w] = acc;
    __syncthreads();

    if (threadIdx.x == 0) {
        float l[E_EXP], p[E_EXP];
        float m = -1e30f;
        #pragma unroll
        for (int e = 0; e < E_EXP; e++) { l[e] = slog[e]; m = fmaxf(m, l[e]); }
        float s = 0.f;
        #pragma unroll
        for (int e = 0; e < E_EXP; e++) { p[e] = expf(l[e] - m); s += p[e]; }
        float inv_s = 1.f / s;
        #pragma unroll
        for (int e = 0; e < E_EXP; e++) p[e] *= inv_s;
        float lse = m + logf(s);
        atomicAdd(&g_zsum, lse * lse);
        #pragma unroll
        for (int e = 0; e < E_EXP; e++) atomicAdd(&g_psum[e], p[e]);

        // top-2 (ties -> lower index, matching lax.top_k)
        int i0 = 0; float p0 = p[0];
        #pragma unroll
        for (int e = 1; e < E_EXP; e++) if (p[e] > p0) { p0 = p[e]; i0 = e; }
        int i1 = -1; float p1 = -1.f;
        #pragma unroll
        for (int e = 0; e < E_EXP; e++) {
            if (e == i0) continue;
            if (p[e] > p1) { p1 = p[e]; i1 = e; }
        }
        float invn = 1.f / (p0 + p1);
        g_sel[2 * t + 0] = i0; g_wsel[2 * t + 0] = p0 * invn;
        g_sel[2 * t + 1] = i1; g_wsel[2 * t + 1] = p1 * invn;
        atomicAdd(&g_cnt[i0], 1);
        atomicAdd(&g_cnt[i1], 1);
    }
}

// ---------------- exclusive scan of counts (tiny) ----------------
__global__ void scan_kernel() {
    if (threadIdx.x == 0) {
        int o = 0;
        for (int e = 0; e < E_EXP; e++) {
            g_base[e] = o; g_cursor[e] = o; o += g_cnt[e];
        }
    }
}

// ---------------- placement: build per-expert contiguous row lists ----------------
__global__ void place_kernel() {
    int t = blockIdx.x * blockDim.x + threadIdx.x;
    if (t >= T_TOK) return;
    #pragma unroll
    for (int k = 0; k < TOPK; k++) {
        int e = g_sel[2 * t + k];
        int pos = atomicAdd(&g_cursor[e], 1);
        g_rowtok[pos] = t;
        g_roww[pos] = g_wsel[2 * t + k];
        g_rowloc[2 * t + k] = pos;
    }
}

__device__ __forceinline__ float gelu_exact(float v) {
    return 0.5f * v * (1.0f + erff(v * 0.70710678118654752f));
}

// ---------------- GEMM1: h = gelu(gather(x) @ w1_e), 128x128x8 fp32 tiles ----------------
__global__ void __launch_bounds__(256, 2)
gemm1_kernel(const float* __restrict__ x, const float* __restrict__ w1) {
    int e = blockIdx.z;
    int n_e = g_cnt[e];
    int base = g_base[e];
    int m0 = blockIdx.y * 128;
    if (m0 >= n_e) return;
    int n0 = blockIdx.x * 128;

    __shared__ float As[8][132];
    __shared__ float Bs[8][128];
    __shared__ int   stok[128];

    if (threadIdx.x < 128) {
        int r = m0 + threadIdx.x;
        stok[threadIdx.x] = (r < n_e) ? g_rowtok[base + r] : -1;
    }
    __syncthreads();

    int tx = threadIdx.x & 15, ty = threadIdx.x >> 4;
    int arow = threadIdx.x >> 1, ak = (threadIdx.x & 1) * 4;
    int bk = threadIdx.x >> 5,   bn = (threadIdx.x & 31) * 4;
    int tokA = stok[arow];

    float acc[8][8];
    #pragma unroll
    for (int i = 0; i < 8; i++)
        #pragma unroll
        for (int j = 0; j < 8; j++) acc[i][j] = 0.f;

    const float* bbase = w1 + (size_t)e * FF_DIM + n0 + bn;

    for (int k0 = 0; k0 < D_DIM; k0 += 8) {
        float4 av = make_float4(0.f, 0.f, 0.f, 0.f);
        if (tokA >= 0)
            av = *(const float4*)(x + (size_t)tokA * D_DIM + k0 + ak);
        As[ak + 0][arow] = av.x; As[ak + 1][arow] = av.y;
        As[ak + 2][arow] = av.z; As[ak + 3][arow] = av.w;

        float4 bv = *(const float4*)(bbase + (size_t)(k0 + bk) * EFF);
        *(float4*)&Bs[bk][bn] = bv;
        __syncthreads();

        #pragma unroll
        for (int kk = 0; kk < 8; kk++) {
            float ra[8], rb[8];
            #pragma unroll
            for (int i = 0; i < 8; i++) ra[i] = As[kk][ty * 8 + i];
            #pragma unroll
            for (int j = 0; j < 8; j++) rb[j] = Bs[kk][tx * 8 + j];
            #pragma unroll
            for (int i = 0; i < 8; i++)
                #pragma unroll
                for (int j = 0; j < 8; j++) acc[i][j] += ra[i] * rb[j];
        }
        __syncthreads();
    }

    #pragma unroll
    for (int i = 0; i < 8; i++) {
        int gr = m0 + ty * 8 + i;
        if (gr < n_e) {
            float* hp = g_h + (size_t)(base + gr) * FF_DIM + n0 + tx * 8;
            float4 v0, v1;
            v0.x = gelu_exact(acc[i][0]); v0.y = gelu_exact(acc[i][1]);
            v0.z = gelu_exact(acc[i][2]); v0.w = gelu_exact(acc[i][3]);
            v1.x = gelu_exact(acc[i][4]); v1.y = gelu_exact(acc[i][5]);
            v1.z = gelu_exact(acc[i][6]); v1.w = gelu_exact(acc[i][7]);
            *(float4*)(hp) = v0;
            *(float4*)(hp + 4) = v1;
        }
    }
}

// ---------------- GEMM2: contrib = h @ w2_e, 128x128x8 fp32 tiles ----------------
__global__ void __launch_bounds__(256, 2)
gemm2_kernel(const float* __restrict__ w2) {
    int e = blockIdx.z;
    int n_e = g_cnt[e];
    int base = g_base[e];
    int m0 = blockIdx.y * 128;
    if (m0 >= n_e) return;
    int n0 = blockIdx.x * 128;

    __shared__ float As[8][132];
    __shared__ float Bs[8][128];

    int tx = threadIdx.x & 15, ty = threadIdx.x >> 4;
    int arow = threadIdx.x >> 1, ak = (threadIdx.x & 1) * 4;
    int bk = threadIdx.x >> 5,   bn = (threadIdx.x & 31) * 4;
    bool avalid = (m0 + arow) < n_e;
    const float* aptr = g_h + (size_t)(base + m0 + arow) * FF_DIM + ak;

    float acc[8][8];
    #pragma unroll
    for (int i = 0; i < 8; i++)
        #pragma unroll
        for (int j = 0; j < 8; j++) acc[i][j] = 0.f;

    const float* bbase = w2 + ((size_t)e * FF_DIM + bk) * D_DIM + n0 + bn;

    for (int k0 = 0; k0 < FF_DIM; k0 += 8) {
        float4 av = make_float4(0.f, 0.f, 0.f, 0.f);
        if (avalid) av = *(const float4*)(aptr + k0);
        As[ak + 0][arow] = av.x; As[ak + 1][arow] = av.y;
        As[ak + 2][arow] = av.z; As[ak + 3][arow] = av.w;

        float4 bv = *(const float4*)(bbase + (size_t)k0 * D_DIM);
        *(float4*)&Bs[bk][bn] = bv;
        __syncthreads();

        #pragma unroll
        for (int kk = 0; kk < 8; kk++) {
            float ra[8], rb[8];
            #pragma unroll
            for (int i = 0; i < 8; i++) ra[i] = As[kk][ty * 8 + i];
            #pragma unroll
            for (int j = 0; j < 8; j++) rb[j] = Bs[kk][tx * 8 + j];
            #pragma unroll
            for (int i = 0; i < 8; i++)
                #pragma unroll
                for (int j = 0; j < 8; j++) acc[i][j] += ra[i] * rb[j];
        }
        __syncthreads();
    }

    #pragma unroll
    for (int i = 0; i < 8; i++) {
        int gr = m0 + ty * 8 + i;
        if (gr < n_e) {
            float* cp = g_contrib + (size_t)(base + gr) * D_DIM + n0 + tx * 8;
            *(float4*)(cp)     = make_float4(acc[i][0], acc[i][1], acc[i][2], acc[i][3]);
            *(float4*)(cp + 4) = make_float4(acc[i][4], acc[i][5], acc[i][6], acc[i][7]);
        }
    }
}

// ---------------- combine: out[t] = w0*contrib[l0] + w1*contrib[l1] ----------------
__global__ void combine_kernel(float* __restrict__ out) {
    int t = blockIdx.x;
    int d = threadIdx.x * 4;
    int l0 = g_rowloc[2 * t + 0];
    int l1 = g_rowloc[2 * t + 1];
    float w0 = g_roww[l0], w1 = g_roww[l1];
    float4 a = *(const float4*)(g_contrib + (size_t)l0 * D_DIM + d);
    float4 b = *(const float4*)(g_contrib + (size_t)l1 * D_DIM + d);
    float4 o;
    o.x = w0 * a.x + w1 * b.x;
    o.y = w0 * a.y + w1 * b.y;
    o.z = w0 * a.z + w1 * b.z;
    o.w = w0 * a.w + w1 * b.w;
    *(float4*)(out + (size_t)t * D_DIM + d) = o;
}

// ---------------- finalize scalars ----------------
__global__ void finalize_kernel(float* __restrict__ out, int out_size) {
    if (threadIdx.x == 0) {
        float z = g_zsum / (float)T_TOK;
        float lb = 0.f;
        for (int e = 0; e < E_EXP; e++) {
            float f_i = (float)g_cnt[e] / (float)(T_TOK * TOPK);
            float p_i = g_psum[e] / (float)T_TOK;
            lb += f_i * p_i;
        }
        lb *= (float)E_EXP;
        out[out_size - 2] = z;
        out[out_size - 1] = lb;
    }
}

// ---------------- launch ----------------
extern "C" void kernel_launch(void* const* d_in, const int* in_sizes, int n_in,
                              void* d_out, int out_size) {
    const float* x  = (const float*)d_in[0];
    const float* rw = (const float*)d_in[1];
    const float* w1 = (const float*)d_in[2];
    const float* w2 = (const float*)d_in[3];
    float* out = (float*)d_out;

    init_kernel<<<1, 32>>>();
    router_kernel<<<T_TOK, 256>>>(x, rw);
    scan_kernel<<<1, 1>>>();
    place_kernel<<<(T_TOK + 255) / 256, 256>>>();

    dim3 g1(FF_DIM / 128, T_TOK / 128, E_EXP);   // (16, 64, 8)
    gemm1_kernel<<<g1, 256>>>(x, w1);
    dim3 g2(D_DIM / 128, T_TOK / 128, E_EXP);    // (8, 64, 8)
    gemm2_kernel<<<g2, 256>>>(w2);

    combine_kernel<<<T_TOK, 256>>>(out);
    finalize_kernel<<<1, 1>>>(out, out_size);
}

// round 8
// speedup vs baseline: 1.2381x; 1.2381x over previous
#include <cuda_runtime.h>
#include <cuda_bf16.h>
#include <math.h>
#include <stdint.h>

// ---------------- problem constants ----------------
#define T_TOK   8192
#define D_DIM   1024
#define E_EXP   8
#define TOPK    2
#define FF_DIM  2048
#define EFF     (E_EXP * FF_DIM)
#define NROWS   (T_TOK * TOPK)      // 16384
#define HPAD    128

// MMA GEMM tiling
#define BM 128
#define BN 128
#define BK 16
#define PART_B   4096                // 128 rows * 32 B of bf16 halves
#define STAGE_SZ (4 * PART_B)        // Ahi | Alo | Bhi | Blo = 16 KB
// 2 stages -> 32 KB static shared

// ---------------- device scratch (total ~202 MB, matching proven R1 level) ----------------
__device__ float g_w1t[(size_t)EFF * D_DIM];             // 67 MB  [e*FF+ff][d] K-major
__device__ float g_h[(size_t)(NROWS + HPAD) * FF_DIM];   // 135 MB gelu rows
__device__ int   g_cnt[E_EXP];
__device__ int   g_base[E_EXP];
__device__ int   g_cursor[E_EXP];
__device__ int   g_rowtok[NROWS];
__device__ float g_roww[NROWS];
__device__ int   g_rowloc[NROWS];
__device__ int   g_sel[NROWS];
__device__ float g_wsel[NROWS];
__device__ float g_zsum;
__device__ float g_psum[E_EXP];

// ---------------- helpers ----------------
__device__ __forceinline__ uint32_t smem_u32(const void* p) {
    uint32_t a;
    asm("{ .reg .u64 t; cvta.to.shared.u64 t, %1; cvt.u32.u64 %0, t; }" : "=r"(a) : "l"(p));
    return a;
}
__device__ __forceinline__ void ldsm4(uint32_t* r, uint32_t addr) {
    asm volatile("ldmatrix.sync.aligned.m8n8.x4.shared.b16 {%0,%1,%2,%3}, [%4];"
                 : "=r"(r[0]), "=r"(r[1]), "=r"(r[2]), "=r"(r[3]) : "r"(addr));
}
__device__ __forceinline__ void mma16816(float* c, const uint32_t* a, const uint32_t* b) {
    asm volatile("mma.sync.aligned.m16n8k16.row.col.f32.bf16.bf16.f32 "
                 "{%0,%1,%2,%3}, {%4,%5,%6,%7}, {%8,%9}, {%0,%1,%2,%3};"
                 : "+f"(c[0]), "+f"(c[1]), "+f"(c[2]), "+f"(c[3])
                 : "r"(a[0]), "r"(a[1]), "r"(a[2]), "r"(a[3]), "r"(b[0]), "r"(b[1]));
}
__device__ __forceinline__ float gelu_exact(float v) {
    return 0.5f * v * (1.0f + erff(v * 0.70710678118654752f));
}
__device__ __forceinline__ uint32_t swz2(int r, int s) {
    return (uint32_t)(r * 32 + (((s ^ r ^ (r >> 2)) & 1) << 4));
}
__device__ __forceinline__ void split8(float4 v0, float4 v1, uint4& hi, uint4& lo) {
    float f[8] = {v0.x, v0.y, v0.z, v0.w, v1.x, v1.y, v1.z, v1.w};
    uint32_t h[8], l[8];
    #pragma unroll
    for (int i = 0; i < 8; i++) {
        __nv_bfloat16 b = __float2bfloat16_rn(f[i]);
        h[i] = (uint32_t)__bfloat16_as_ushort(b);
        l[i] = (uint32_t)__bfloat16_as_ushort(__float2bfloat16_rn(f[i] - __bfloat162float(b)));
    }
    hi = make_uint4(h[0] | (h[1] << 16), h[2] | (h[3] << 16), h[4] | (h[5] << 16), h[6] | (h[7] << 16));
    lo = make_uint4(l[0] | (l[1] << 16), l[2] | (l[3] << 16), l[4] | (l[5] << 16), l[6] | (l[7] << 16));
}

// ---------------- init ----------------
__global__ void init_kernel() {
    int i = threadIdx.x;
    if (i < E_EXP) { g_cnt[i] = 0; g_psum[i] = 0.f; }
    if (i == 0)    { g_zsum = 0.f; }
}

__global__ void zero_out_kernel(float* __restrict__ out) {
    size_t i = ((size_t)blockIdx.x * blockDim.x + threadIdx.x) * 4;
    *(float4*)(out + i) = make_float4(0.f, 0.f, 0.f, 0.f);
}

// ---------------- router ----------------
__global__ void router_kernel(const float* __restrict__ x,
                              const float* __restrict__ rw) {
    __shared__ float sx[D_DIM];
    __shared__ float slog[E_EXP];
    int t = blockIdx.x;
    const float* xr = x + (size_t)t * D_DIM;
    for (int i = threadIdx.x; i < D_DIM; i += blockDim.x) sx[i] = xr[i];
    __syncthreads();

    int w = threadIdx.x >> 5, lane = threadIdx.x & 31;
    float acc = 0.f;
    const float* we = rw + w * D_DIM;
    for (int i = lane; i < D_DIM; i += 32) acc += sx[i] * we[i];
    #pragma unroll
    for (int o = 16; o; o >>= 1) acc += __shfl_xor_sync(0xffffffffu, acc, o);
    if (lane == 0) slog[w] = acc;
    __syncthreads();

    if (threadIdx.x == 0) {
        float l[E_EXP], p[E_EXP];
        float m = -1e30f;
        #pragma unroll
        for (int e = 0; e < E_EXP; e++) { l[e] = slog[e]; m = fmaxf(m, l[e]); }
        float s = 0.f;
        #pragma unroll
        for (int e = 0; e < E_EXP; e++) { p[e] = expf(l[e] - m); s += p[e]; }
        float inv_s = 1.f / s;
        #pragma unroll
        for (int e = 0; e < E_EXP; e++) p[e] *= inv_s;
        float lse = m + logf(s);
        atomicAdd(&g_zsum, lse * lse);
        #pragma unroll
        for (int e = 0; e < E_EXP; e++) atomicAdd(&g_psum[e], p[e]);

        int i0 = 0; float p0 = p[0];
        #pragma unroll
        for (int e = 1; e < E_EXP; e++) if (p[e] > p0) { p0 = p[e]; i0 = e; }
        int i1 = -1; float p1 = -1.f;
        #pragma unroll
        for (int e = 0; e < E_EXP; e++) {
            if (e == i0) continue;
            if (p[e] > p1) { p1 = p[e]; i1 = e; }
        }
        float invn = 1.f / (p0 + p1);
        g_sel[2 * t + 0] = i0; g_wsel[2 * t + 0] = p0 * invn;
        g_sel[2 * t + 1] = i1; g_wsel[2 * t + 1] = p1 * invn;
        atomicAdd(&g_cnt[i0], 1);
        atomicAdd(&g_cnt[i1], 1);
    }
}

__global__ void scan_kernel() {
    if (threadIdx.x == 0) {
        int o = 0;
        for (int e = 0; e < E_EXP; e++) { g_base[e] = o; g_cursor[e] = o; o += g_cnt[e]; }
    }
}

__global__ void place_kernel() {
    int t = blockIdx.x * blockDim.x + threadIdx.x;
    if (t >= T_TOK) return;
    #pragma unroll
    for (int k = 0; k < TOPK; k++) {
        int e = g_sel[2 * t + k];
        int pos = atomicAdd(&g_cursor[e], 1);
        g_rowtok[pos] = t;
        g_roww[pos] = g_wsel[2 * t + k];
        g_rowloc[2 * t + k] = pos;
    }
}

// ---------------- w1 transpose: [D][EFF] -> [EFF][D] fp32 ----------------
__global__ void transpose_w1_kernel(const float* __restrict__ w1) {
    __shared__ float tile[32][33];
    int n0 = blockIdx.x * 32, k0 = blockIdx.y * 32;
    int tx = threadIdx.x, ty = threadIdx.y;
    #pragma unroll
    for (int i = 0; i < 4; i++)
        tile[ty + i * 8][tx] = w1[(size_t)(k0 + ty + i * 8) * EFF + n0 + tx];
    __syncthreads();
    #pragma unroll
    for (int i = 0; i < 4; i++)
        g_w1t[(size_t)(n0 + ty + i * 8) * D_DIM + k0 + tx] = tile[tx][ty + i * 8];
}

// ================= GEMM1: MMA bf16 3-term (h = gelu(gather(x) @ w1_e)) ==========
__global__ void __launch_bounds__(256, 1)
gemm1_mma(const float* __restrict__ x) {
    __shared__ __align__(16) char smem[2 * STAGE_SZ];   // 32 KB

    int e = blockIdx.z;
    int n_e = g_cnt[e], base = g_base[e];
    int m0 = blockIdx.y * BM;
    if (m0 >= n_e) return;
    int n0 = blockIdx.x * BN;

    int tid = threadIdx.x, lane = tid & 31, wid = tid >> 5;
    uint32_t sb = smem_u32(smem);

    int crow = tid >> 1, cseg = tid & 1;
    int arow_g = m0 + crow;
    int tok = (arow_g < n_e) ? g_rowtok[base + arow_g] : 0;
    const float* aptr = x + (size_t)tok * D_DIM + cseg * 8;
    const float* bptr = g_w1t + ((size_t)e * FF_DIM + n0 + crow) * D_DIM + cseg * 8;
    uint32_t wdst = swz2(crow, cseg);

    const int NCH = D_DIM / BK;   // 64

    float4 ra0, ra1, rb0, rb1;
    auto loadc = [&](int ch) {
        int k0 = ch * BK;
        ra0 = *(const float4*)(aptr + k0);
        ra1 = *(const float4*)(aptr + k0 + 4);
        rb0 = *(const float4*)(bptr + k0);
        rb1 = *(const float4*)(bptr + k0 + 4);
    };
    auto storec = [&](int s) {
        char* p = smem + s * STAGE_SZ + wdst;
        uint4 hi, lo;
        split8(ra0, ra1, hi, lo);
        *(uint4*)(p)              = hi;
        *(uint4*)(p + PART_B)     = lo;
        split8(rb0, rb1, hi, lo);
        *(uint4*)(p + 2 * PART_B) = hi;
        *(uint4*)(p + 3 * PART_B) = lo;
    };

    loadc(0);
    storec(0);
    loadc(1);
    __syncthreads();

    int warp_m = (wid & 1) * 64, warp_n = (wid >> 1) * 32;

    float acc[4][4][4];
    #pragma unroll
    for (int i = 0; i < 4; i++)
        #pragma unroll
        for (int j = 0; j < 4; j++)
            #pragma unroll
            for (int q = 0; q < 4; q++) acc[i][j][q] = 0.f;

    uint32_t aphys = swz2(warp_m + (lane & 15), lane >> 4);
    uint32_t bphys = swz2(warp_n + (lane & 7) + ((lane & 16) ? 8 : 0), (lane >> 3) & 1);

    for (int ch = 0; ch < NCH; ch++) {
        if (ch + 1 < NCH) storec((ch + 1) & 1);
        if (ch + 2 < NCH) loadc(ch + 2);

        uint32_t st = sb + (ch & 1) * STAGE_SZ;
        uint32_t ah[4][4], al[4][4], bh[4][2], bl[4][2];
        #pragma unroll
        for (int mi = 0; mi < 4; mi++) {
            ldsm4(ah[mi], st + aphys + mi * 512);
            ldsm4(al[mi], st + PART_B + aphys + mi * 512);
        }
        #pragma unroll
        for (int ng = 0; ng < 2; ng++) {
            uint32_t r[4];
            ldsm4(r, st + 2 * PART_B + bphys + ng * 512);
            bh[ng * 2][0] = r[0]; bh[ng * 2][1] = r[1];
            bh[ng * 2 + 1][0] = r[2]; bh[ng * 2 + 1][1] = r[3];
            ldsm4(r, st + 3 * PART_B + bphys + ng * 512);
            bl[ng * 2][0] = r[0]; bl[ng * 2][1] = r[1];
            bl[ng * 2 + 1][0] = r[2]; bl[ng * 2 + 1][1] = r[3];
        }
        #pragma unroll
        for (int mi = 0; mi < 4; mi++)
            #pragma unroll
            for (int ni = 0; ni < 4; ni++) mma16816(acc[mi][ni], ah[mi], bh[ni]);
        #pragma unroll
        for (int mi = 0; mi < 4; mi++)
            #pragma unroll
            for (int ni = 0; ni < 4; ni++) mma16816(acc[mi][ni], ah[mi], bl[ni]);
        #pragma unroll
        for (int mi = 0; mi < 4; mi++)
            #pragma unroll
            for (int ni = 0; ni < 4; ni++) mma16816(acc[mi][ni], al[mi], bh[ni]);
        __syncthreads();
    }

    // epilogue: gelu -> fp32 g_h
    #pragma unroll
    for (int mi = 0; mi < 4; mi++) {
        int gr0 = m0 + warp_m + mi * 16 + (lane >> 2);
        int gr1 = gr0 + 8;
        bool v0 = gr0 < n_e, v1 = gr1 < n_e;
        #pragma unroll
        for (int ni = 0; ni < 4; ni++) {
            int c_col = n0 + warp_n + ni * 8 + (lane & 3) * 2;
            float* a4 = acc[mi][ni];
            if (v0) *(float2*)(g_h + (size_t)(base + gr0) * FF_DIM + c_col) =
                    make_float2(gelu_exact(a4[0]), gelu_exact(a4[1]));
            if (v1) *(float2*)(g_h + (size_t)(base + gr1) * FF_DIM + c_col) =
                    make_float2(gelu_exact(a4[2]), gelu_exact(a4[3]));
        }
    }
}

// ================= GEMM2: proven fp32 SIMT, fused weighted scatter ==============
__global__ void __launch_bounds__(256, 2)
gemm2_kernel(const float* __restrict__ w2, float* __restrict__ out) {
    int e = blockIdx.z;
    int n_e = g_cnt[e];
    int base = g_base[e];
    int m0 = blockIdx.y * 128;
    if (m0 >= n_e) return;
    int n0 = blockIdx.x * 128;

    __shared__ float As[8][132];
    __shared__ float Bs[8][128];

    int tx = threadIdx.x & 15, ty = threadIdx.x >> 4;
    int arow = threadIdx.x >> 1, ak = (threadIdx.x & 1) * 4;
    int bk = threadIdx.x >> 5,   bn = (threadIdx.x & 31) * 4;
    bool avalid = (m0 + arow) < n_e;
    const float* aptr = g_h + (size_t)(base + m0 + arow) * FF_DIM + ak;

    float acc[8][8];
    #pragma unroll
    for (int i = 0; i < 8; i++)
        #pragma unroll
        for (int j = 0; j < 8; j++) acc[i][j] = 0.f;

    const float* bbase = w2 + ((size_t)e * FF_DIM + bk) * D_DIM + n0 + bn;

    for (int k0 = 0; k0 < FF_DIM; k0 += 8) {
        float4 av = make_float4(0.f, 0.f, 0.f, 0.f);
        if (avalid) av = *(const float4*)(aptr + k0);
        As[ak + 0][arow] = av.x; As[ak + 1][arow] = av.y;
        As[ak + 2][arow] = av.z; As[ak + 3][arow] = av.w;

        float4 bv = *(const float4*)(bbase + (size_t)k0 * D_DIM);
        *(float4*)&Bs[bk][bn] = bv;
        __syncthreads();

        #pragma unroll
        for (int kk = 0; kk < 8; kk++) {
            float ra[8], rb[8];
            #pragma unroll
            for (int i = 0; i < 8; i++) ra[i] = As[kk][ty * 8 + i];
            #pragma unroll
            for (int j = 0; j < 8; j++) rb[j] = Bs[kk][tx * 8 + j];
            #pragma unroll
            for (int i = 0; i < 8; i++)
                #pragma unroll
                for (int j = 0; j < 8; j++) acc[i][j] += ra[i] * rb[j];
        }
        __syncthreads();
    }

    #pragma unroll
    for (int i = 0; i < 8; i++) {
        int gr = m0 + ty * 8 + i;
        if (gr < n_e) {
            int tok = g_rowtok[base + gr];
            float w = g_roww[base + gr];
            float* op = out + (size_t)tok * D_DIM + n0 + tx * 8;
            #pragma unroll
            for (int j = 0; j < 8; j++) atomicAdd(op + j, w * acc[i][j]);
        }
    }
}

// ---------------- finalize scalars ----------------
__global__ void finalize_kernel(float* __restrict__ out, int out_size) {
    if (threadIdx.x == 0) {
        float z = g_zsum / (float)T_TOK;
        float lb = 0.f;
        for (int e = 0; e < E_EXP; e++) {
            float f_i = (float)g_cnt[e] / (float)(T_TOK * TOPK);
            float p_i = g_psum[e] / (float)T_TOK;
            lb += f_i * p_i;
        }
        lb *= (float)E_EXP;
        out[out_size - 2] = z;
        out[out_size - 1] = lb;
    }
}

// ---------------- launch ----------------
extern "C" void kernel_launch(void* const* d_in, const int* in_sizes, int n_in,
                              void* d_out, int out_size) {
    const float* x  = (const float*)d_in[0];
    const float* rw = (const float*)d_in[1];
    const float* w1 = (const float*)d_in[2];
    const float* w2 = (const float*)d_in[3];
    float* out = (float*)d_out;

    init_kernel<<<1, 32>>>();
    router_kernel<<<T_TOK, 256>>>(x, rw);
    scan_kernel<<<1, 1>>>();
    place_kernel<<<(T_TOK + 255) / 256, 256>>>();

    transpose_w1_kernel<<<dim3(EFF / 32, D_DIM / 32), dim3(32, 8)>>>(w1);

    gemm1_mma<<<dim3(FF_DIM / BN, T_TOK / BM, E_EXP), 256>>>(x);

    zero_out_kernel<<<(T_TOK * D_DIM / 4) / 256, 256>>>(out);
    gemm2_kernel<<<dim3(D_DIM / 128, T_TOK / 128, E_EXP), 256>>>(w2, out);

    finalize_kernel<<<1, 1>>>(out, out_size);
}

// round 11
// speedup vs baseline: 1.7569x; 1.4190x over previous
#include <cuda_runtime.h>
#include <cuda_bf16.h>
#include <math.h>
#include <stdint.h>

// ---------------- problem constants ----------------
#define T_TOK   8192
#define D_DIM   1024
#define E_EXP   8
#define TOPK    2
#define FF_DIM  2048
#define EFF     (E_EXP * FF_DIM)
#define NROWS   (T_TOK * TOPK)      // 16384
#define HPAD    128

// MMA GEMM tiling
#define BM 128
#define BN 128
#define BK 16
#define PART_B   4096                // 128 rows * 32 B of bf16 halves
#define STAGE_SZ (4 * PART_B)        // Ahi | Alo | Bhi | Blo = 16 KB
// 2 stages -> 32 KB static shared

// ---------------- device scratch (~202 MB, proven-safe level) ----------------
// g_wt holds w1t (K-major) for GEMM1, then is REUSED for w2t before GEMM2.
__device__ float g_wt[(size_t)EFF * D_DIM];              // 67 MB
__device__ float g_h[(size_t)(NROWS + HPAD) * FF_DIM];   // 135 MB gelu rows
__device__ int   g_cnt[E_EXP];
__device__ int   g_base[E_EXP];
__device__ int   g_cursor[E_EXP];
__device__ int   g_rowtok[NROWS];
__device__ float g_roww[NROWS];
__device__ int   g_rowloc[NROWS];
__device__ int   g_sel[NROWS];
__device__ float g_wsel[NROWS];
__device__ float g_zsum;
__device__ float g_psum[E_EXP];

// ---------------- helpers ----------------
__device__ __forceinline__ uint32_t smem_u32(const void* p) {
    uint32_t a;
    asm("{ .reg .u64 t; cvta.to.shared.u64 t, %1; cvt.u32.u64 %0, t; }" : "=r"(a) : "l"(p));
    return a;
}
__device__ __forceinline__ void ldsm4(uint32_t* r, uint32_t addr) {
    asm volatile("ldmatrix.sync.aligned.m8n8.x4.shared.b16 {%0,%1,%2,%3}, [%4];"
                 : "=r"(r[0]), "=r"(r[1]), "=r"(r[2]), "=r"(r[3]) : "r"(addr));
}
__device__ __forceinline__ void mma16816(float* c, const uint32_t* a, const uint32_t* b) {
    asm volatile("mma.sync.aligned.m16n8k16.row.col.f32.bf16.bf16.f32 "
                 "{%0,%1,%2,%3}, {%4,%5,%6,%7}, {%8,%9}, {%0,%1,%2,%3};"
                 : "+f"(c[0]), "+f"(c[1]), "+f"(c[2]), "+f"(c[3])
                 : "r"(a[0]), "r"(a[1]), "r"(a[2]), "r"(a[3]), "r"(b[0]), "r"(b[1]));
}
__device__ __forceinline__ float gelu_exact(float v) {
    return 0.5f * v * (1.0f + erff(v * 0.70710678118654752f));
}
__device__ __forceinline__ uint32_t swz2(int r, int s) {
    return (uint32_t)(r * 32 + (((s ^ r ^ (r >> 2)) & 1) << 4));
}
__device__ __forceinline__ void split8(float4 v0, float4 v1, uint4& hi, uint4& lo) {
    float f[8] = {v0.x, v0.y, v0.z, v0.w, v1.x, v1.y, v1.z, v1.w};
    uint32_t h[8], l[8];
    #pragma unroll
    for (int i = 0; i < 8; i++) {
        __nv_bfloat16 b = __float2bfloat16_rn(f[i]);
        h[i] = (uint32_t)__bfloat16_as_ushort(b);
        l[i] = (uint32_t)__bfloat16_as_ushort(__float2bfloat16_rn(f[i] - __bfloat162float(b)));
    }
    hi = make_uint4(h[0] | (h[1] << 16), h[2] | (h[3] << 16), h[4] | (h[5] << 16), h[6] | (h[7] << 16));
    lo = make_uint4(l[0] | (l[1] << 16), l[2] | (l[3] << 16), l[4] | (l[5] << 16), l[6] | (l[7] << 16));
}

// ---------------- init ----------------
__global__ void init_kernel() {
    int i = threadIdx.x;
    if (i < E_EXP) { g_cnt[i] = 0; g_psum[i] = 0.f; }
    if (i == 0)    { g_zsum = 0.f; }
}

__global__ void zero_out_kernel(float* __restrict__ out) {
    size_t i = ((size_t)blockIdx.x * blockDim.x + threadIdx.x) * 4;
    *(float4*)(out + i) = make_float4(0.f, 0.f, 0.f, 0.f);
}

// ---------------- router ----------------
__global__ void router_kernel(const float* __restrict__ x,
                              const float* __restrict__ rw) {
    __shared__ float sx[D_DIM];
    __shared__ float slog[E_EXP];
    int t = blockIdx.x;
    const float* xr = x + (size_t)t * D_DIM;
    for (int i = threadIdx.x; i < D_DIM; i += blockDim.x) sx[i] = xr[i];
    __syncthreads();

    int w = threadIdx.x >> 5, lane = threadIdx.x & 31;
    float acc = 0.f;
    const float* we = rw + w * D_DIM;
    for (int i = lane; i < D_DIM; i += 32) acc += sx[i] * we[i];
    #pragma unroll
    for (int o = 16; o; o >>= 1) acc += __shfl_xor_sync(0xffffffffu, acc, o);
    if (lane == 0) slog[w] = acc;
    __syncthreads();

    if (threadIdx.x == 0) {
        float l[E_EXP], p[E_EXP];
        float m = -1e30f;
        #pragma unroll
        for (int e = 0; e < E_EXP; e++) { l[e] = slog[e]; m = fmaxf(m, l[e]); }
        float s = 0.f;
        #pragma unroll
        for (int e = 0; e < E_EXP; e++) { p[e] = expf(l[e] - m); s += p[e]; }
        float inv_s = 1.f / s;
        #pragma unroll
        for (int e = 0; e < E_EXP; e++) p[e] *= inv_s;
        float lse = m + logf(s);
        atomicAdd(&g_zsum, lse * lse);
        #pragma unroll
        for (int e = 0; e < E_EXP; e++) atomicAdd(&g_psum[e], p[e]);

        int i0 = 0; float p0 = p[0];
        #pragma unroll
        for (int e = 1; e < E_EXP; e++) if (p[e] > p0) { p0 = p[e]; i0 = e; }
        int i1 = -1; float p1 = -1.f;
        #pragma unroll
        for (int e = 0; e < E_EXP; e++) {
            if (e == i0) continue;
            if (p[e] > p1) { p1 = p[e]; i1 = e; }
        }
        float invn = 1.f / (p0 + p1);
        g_sel[2 * t + 0] = i0; g_wsel[2 * t + 0] = p0 * invn;
        g_sel[2 * t + 1] = i1; g_wsel[2 * t + 1] = p1 * invn;
        atomicAdd(&g_cnt[i0], 1);
        atomicAdd(&g_cnt[i1], 1);
    }
}

__global__ void scan_kernel() {
    if (threadIdx.x == 0) {
        int o = 0;
        for (int e = 0; e < E_EXP; e++) { g_base[e] = o; g_cursor[e] = o; o += g_cnt[e]; }
    }
}

__global__ void place_kernel() {
    int t = blockIdx.x * blockDim.x + threadIdx.x;
    if (t >= T_TOK) return;
    #pragma unroll
    for (int k = 0; k < TOPK; k++) {
        int e = g_sel[2 * t + k];
        int pos = atomicAdd(&g_cursor[e], 1);
        g_rowtok[pos] = t;
        g_roww[pos] = g_wsel[2 * t + k];
        g_rowloc[2 * t + k] = pos;
    }
}

// ---------------- transposes into the shared K-major buffer ----------------
// w1 [D][EFF] -> g_wt rows [e*FF+ff][d]
__global__ void transpose_w1_kernel(const float* __restrict__ w1) {
    __shared__ float tile[32][33];
    int n0 = blockIdx.x * 32, k0 = blockIdx.y * 32;
    int tx = threadIdx.x, ty = threadIdx.y;
    #pragma unroll
    for (int i = 0; i < 4; i++)
        tile[ty + i * 8][tx] = w1[(size_t)(k0 + ty + i * 8) * EFF + n0 + tx];
    __syncthreads();
    #pragma unroll
    for (int i = 0; i < 4; i++)
        g_wt[(size_t)(n0 + ty + i * 8) * D_DIM + k0 + tx] = tile[tx][ty + i * 8];
}

// w2 [e*FF+k][D] -> g_wt rows [e*D+d][ff]   (runs AFTER gemm1 consumed w1t)
__global__ void transpose_w2_kernel(const float* __restrict__ w2) {
    __shared__ float tile[32][33];
    int c0 = blockIdx.x * 32, r0 = blockIdx.y * 32;
    int tx = threadIdx.x, ty = threadIdx.y;
    #pragma unroll
    for (int i = 0; i < 4; i++)
        tile[ty + i * 8][tx] = w2[(size_t)(r0 + ty + i * 8) * D_DIM + c0 + tx];
    __syncthreads();
    int e = r0 >> 11, kl = r0 & (FF_DIM - 1);
    #pragma unroll
    for (int i = 0; i < 4; i++)
        g_wt[(size_t)(e * D_DIM + c0 + ty + i * 8) * FF_DIM + kl + tx] = tile[tx][ty + i * 8];
}

// ================= MMA GEMM core (bf16 3-term split, fp32 sources) ==============
// IS_GEMM1: A = gather(x via xin) [K=D], B = g_wt(w1t), epilogue gelu -> g_h
// else:     A = g_h rows [K=FF],  B = g_wt(w2t), epilogue weighted atomicAdd -> out
// NOTE: device globals (g_h, g_wt) are referenced INSIDE the kernel only —
// passing a __device__ symbol as a host-side kernel argument is UB (R9 bug).
template <int KTOT, bool IS_GEMM1>
__global__ void __launch_bounds__(256, 1)
gemm_mma(const float* __restrict__ xin, float* __restrict__ out) {
    __shared__ __align__(16) char smem[2 * STAGE_SZ];   // 32 KB

    const int N_TOTAL = IS_GEMM1 ? FF_DIM : D_DIM;

    int e = blockIdx.z;
    int n_e = g_cnt[e], base = g_base[e];
    int m0 = blockIdx.y * BM;
    if (m0 >= n_e) return;
    int n0 = blockIdx.x * BN;

    int tid = threadIdx.x, lane = tid & 31, wid = tid >> 5;
    uint32_t sb = smem_u32(smem);

    int crow = tid >> 1, cseg = tid & 1;
    const float* aptr;
    if (IS_GEMM1) {
        int arow_g = m0 + crow;
        int tok = (arow_g < n_e) ? g_rowtok[base + arow_g] : 0;
        aptr = xin + (size_t)tok * KTOT + cseg * 8;
    } else {
        aptr = g_h + (size_t)(base + m0 + crow) * KTOT + cseg * 8;
    }
    const float* bptr = g_wt + ((size_t)e * N_TOTAL + n0 + crow) * KTOT + cseg * 8;
    uint32_t wdst = swz2(crow, cseg);

    const int NCH = KTOT / BK;

    float4 ra0, ra1, rb0, rb1;
    auto loadc = [&](int ch) {
        int k0 = ch * BK;
        ra0 = *(const float4*)(aptr + k0);
        ra1 = *(const float4*)(aptr + k0 + 4);
        rb0 = *(const float4*)(bptr + k0);
        rb1 = *(const float4*)(bptr + k0 + 4);
    };
    auto storec = [&](int s) {
        char* p = smem + s * STAGE_SZ + wdst;
        uint4 hi, lo;
        split8(ra0, ra1, hi, lo);
        *(uint4*)(p)              = hi;
        *(uint4*)(p + PART_B)     = lo;
        split8(rb0, rb1, hi, lo);
        *(uint4*)(p + 2 * PART_B) = hi;
        *(uint4*)(p + 3 * PART_B) = lo;
    };

    loadc(0);
    storec(0);
    loadc(1);
    __syncthreads();

    int warp_m = (wid & 1) * 64, warp_n = (wid >> 1) * 32;

    float acc[4][4][4];
    #pragma unroll
    for (int i = 0; i < 4; i++)
        #pragma unroll
        for (int j = 0; j < 4; j++)
            #pragma unroll
            for (int q = 0; q < 4; q++) acc[i][j][q] = 0.f;

    uint32_t aphys = swz2(warp_m + (lane & 15), lane >> 4);
    uint32_t bphys = swz2(warp_n + (lane & 7) + ((lane & 16) ? 8 : 0), (lane >> 3) & 1);

    for (int ch = 0; ch < NCH; ch++) {
        if (ch + 1 < NCH) storec((ch + 1) & 1);
        if (ch + 2 < NCH) loadc(ch + 2);

        uint32_t st = sb + (ch & 1) * STAGE_SZ;
        uint32_t ah[4][4], al[4][4], bh[4][2], bl[4][2];
        #pragma unroll
        for (int mi = 0; mi < 4; mi++) {
            ldsm4(ah[mi], st + aphys + mi * 512);
            ldsm4(al[mi], st + PART_B + aphys + mi * 512);
        }
        #pragma unroll
        for (int ng = 0; ng < 2; ng++) {
            uint32_t r[4];
            ldsm4(r, st + 2 * PART_B + bphys + ng * 512);
            bh[ng * 2][0] = r[0]; bh[ng * 2][1] = r[1];
            bh[ng * 2 + 1][0] = r[2]; bh[ng * 2 + 1][1] = r[3];
            ldsm4(r, st + 3 * PART_B + bphys + ng * 512);
            bl[ng * 2][0] = r[0]; bl[ng * 2][1] = r[1];
            bl[ng * 2 + 1][0] = r[2]; bl[ng * 2 + 1][1] = r[3];
        }
        #pragma unroll
        for (int mi = 0; mi < 4; mi++)
            #pragma unroll
            for (int ni = 0; ni < 4; ni++) mma16816(acc[mi][ni], ah[mi], bh[ni]);
        #pragma unroll
        for (int mi = 0; mi < 4; mi++)
            #pragma unroll
            for (int ni = 0; ni < 4; ni++) mma16816(acc[mi][ni], ah[mi], bl[ni]);
        #pragma unroll
        for (int mi = 0; mi < 4; mi++)
            #pragma unroll
            for (int ni = 0; ni < 4; ni++) mma16816(acc[mi][ni], al[mi], bh[ni]);
        __syncthreads();
    }

    // ---------------- epilogue ----------------
    #pragma unroll
    for (int mi = 0; mi < 4; mi++) {
        int gr0 = m0 + warp_m + mi * 16 + (lane >> 2);
        int gr1 = gr0 + 8;
        bool v0 = gr0 < n_e, v1 = gr1 < n_e;
        int tok0 = 0, tok1 = 0; float wgt0 = 0.f, wgt1 = 0.f;
        if (!IS_GEMM1) {
            if (v0) { tok0 = g_rowtok[base + gr0]; wgt0 = g_roww[base + gr0]; }
            if (v1) { tok1 = g_rowtok[base + gr1]; wgt1 = g_roww[base + gr1]; }
        }
        #pragma unroll
        for (int ni = 0; ni < 4; ni++) {
            int c_col = n0 + warp_n + ni * 8 + (lane & 3) * 2;
            float* a4 = acc[mi][ni];
            if (IS_GEMM1) {
                if (v0) *(float2*)(g_h + (size_t)(base + gr0) * FF_DIM + c_col) =
                        make_float2(gelu_exact(a4[0]), gelu_exact(a4[1]));
                if (v1) *(float2*)(g_h + (size_t)(base + gr1) * FF_DIM + c_col) =
                        make_float2(gelu_exact(a4[2]), gelu_exact(a4[3]));
            } else {
                if (v0) {
                    float* op = out + (size_t)tok0 * D_DIM + c_col;
                    atomicAdd(op,     wgt0 * a4[0]);
                    atomicAdd(op + 1, wgt0 * a4[1]);
                }
                if (v1) {
                    float* op = out + (size_t)tok1 * D_DIM + c_col;
                    atomicAdd(op,     wgt1 * a4[2]);
                    atomicAdd(op + 1, wgt1 * a4[3]);
                }
            }
        }
    }
}

// ---------------- finalize scalars ----------------
__global__ void finalize_kernel(float* __restrict__ out, int out_size) {
    if (threadIdx.x == 0) {
        float z = g_zsum / (float)T_TOK;
        float lb = 0.f;
        for (int e = 0; e < E_EXP; e++) {
            float f_i = (float)g_cnt[e] / (float)(T_TOK * TOPK);
            float p_i = g_psum[e] / (float)T_TOK;
            lb += f_i * p_i;
        }
        lb *= (float)E_EXP;
        out[out_size - 2] = z;
        out[out_size - 1] = lb;
    }
}

// ---------------- launch ----------------
extern "C" void kernel_launch(void* const* d_in, const int* in_sizes, int n_in,
                              void* d_out, int out_size) {
    const float* x  = (const float*)d_in[0];
    const float* rw = (const float*)d_in[1];
    const float* w1 = (const float*)d_in[2];
    const float* w2 = (const float*)d_in[3];
    float* out = (float*)d_out;

    init_kernel<<<1, 32>>>();
    router_kernel<<<T_TOK, 256>>>(x, rw);
    scan_kernel<<<1, 1>>>();
    place_kernel<<<(T_TOK + 255) / 256, 256>>>();

    transpose_w1_kernel<<<dim3(EFF / 32, D_DIM / 32), dim3(32, 8)>>>(w1);

    // GEMM1 (consumes g_wt as w1t, writes g_h)
    gemm_mma<D_DIM, true><<<dim3(FF_DIM / BN, T_TOK / BM, E_EXP), 256>>>(x, out);

    // reuse g_wt for w2t, then GEMM2 with fused weighted scatter into out
    transpose_w2_kernel<<<dim3(D_DIM / 32, EFF / 32), dim3(32, 8)>>>(w2);
    zero_out_kernel<<<(T_TOK * D_DIM / 4) / 256, 256>>>(out);
    gemm_mma<FF_DIM, false><<<dim3(D_DIM / BN, T_TOK / BM, E_EXP), 256>>>(x, out);

    finalize_kernel<<<1, 1>>>(out, out_size);
}

// round 12
// speedup vs baseline: 2.1372x; 1.2164x over previous
#include <cuda_runtime.h>
#include <cuda_bf16.h>
#include <math.h>
#include <stdint.h>

// ---------------- problem constants ----------------
#define T_TOK   8192
#define D_DIM   1024
#define E_EXP   8
#define TOPK    2
#define FF_DIM  2048
#define EFF     (E_EXP * FF_DIM)
#define NROWS   (T_TOK * TOPK)      // 16384
#define HPAD    128

// MMA GEMM tiling
#define BM 128
#define BN 128
#define BK 16
#define PART_B   4096                // 128 rows * 32 B of bf16 halves
#define STAGE_SZ (4 * PART_B)        // Ahi | Alo | Bhi | Blo = 16 KB
// 2 stages -> 32 KB static shared

// ---------------- device scratch (~236 MB; no symbol ever crosses launch) ----------------
__device__ __nv_bfloat16 g_x_hi[(size_t)T_TOK * D_DIM];            // 16.8 MB
__device__ __nv_bfloat16 g_x_lo[(size_t)T_TOK * D_DIM];            // 16.8 MB
__device__ __nv_bfloat16 g_wt_hi[(size_t)EFF * D_DIM];             // 33.5 MB (w1t, then w2t)
__device__ __nv_bfloat16 g_wt_lo[(size_t)EFF * D_DIM];             // 33.5 MB
__device__ __nv_bfloat16 g_h_hi[(size_t)(NROWS + HPAD) * FF_DIM];  // 67.6 MB
__device__ __nv_bfloat16 g_h_lo[(size_t)(NROWS + HPAD) * FF_DIM];  // 67.6 MB
__device__ int   g_cnt[E_EXP];
__device__ int   g_base[E_EXP];
__device__ int   g_cursor[E_EXP];
__device__ int   g_rowtok[NROWS];
__device__ float g_roww[NROWS];
__device__ int   g_rowloc[NROWS];
__device__ int   g_sel[NROWS];
__device__ float g_wsel[NROWS];
__device__ float g_zsum;
__device__ float g_psum[E_EXP];

// ---------------- helpers ----------------
__device__ __forceinline__ uint32_t smem_u32(const void* p) {
    uint32_t a;
    asm("{ .reg .u64 t; cvta.to.shared.u64 t, %1; cvt.u32.u64 %0, t; }" : "=r"(a) : "l"(p));
    return a;
}
__device__ __forceinline__ void ldsm4(uint32_t* r, uint32_t addr) {
    asm volatile("ldmatrix.sync.aligned.m8n8.x4.shared.b16 {%0,%1,%2,%3}, [%4];"
                 : "=r"(r[0]), "=r"(r[1]), "=r"(r[2]), "=r"(r[3]) : "r"(addr));
}
__device__ __forceinline__ void mma16816(float* c, const uint32_t* a, const uint32_t* b) {
    asm volatile("mma.sync.aligned.m16n8k16.row.col.f32.bf16.bf16.f32 "
                 "{%0,%1,%2,%3}, {%4,%5,%6,%7}, {%8,%9}, {%0,%1,%2,%3};"
                 : "+f"(c[0]), "+f"(c[1]), "+f"(c[2]), "+f"(c[3])
                 : "r"(a[0]), "r"(a[1]), "r"(a[2]), "r"(a[3]), "r"(b[0]), "r"(b[1]));
}
__device__ __forceinline__ float gelu_exact(float v) {
    return 0.5f * v * (1.0f + erff(v * 0.70710678118654752f));
}
__device__ __forceinline__ uint32_t swz2(int r, int s) {
    return (uint32_t)(r * 32 + (((s ^ r ^ (r >> 2)) & 1) << 4));
}
__device__ __forceinline__ void split8(float4 v0, float4 v1, uint4& hi, uint4& lo) {
    float f[8] = {v0.x, v0.y, v0.z, v0.w, v1.x, v1.y, v1.z, v1.w};
    uint32_t h[8], l[8];
    #pragma unroll
    for (int i = 0; i < 8; i++) {
        __nv_bfloat16 b = __float2bfloat16_rn(f[i]);
        h[i] = (uint32_t)__bfloat16_as_ushort(b);
        l[i] = (uint32_t)__bfloat16_as_ushort(__float2bfloat16_rn(f[i] - __bfloat162float(b)));
    }
    hi = make_uint4(h[0] | (h[1] << 16), h[2] | (h[3] << 16), h[4] | (h[5] << 16), h[6] | (h[7] << 16));
    lo = make_uint4(l[0] | (l[1] << 16), l[2] | (l[3] << 16), l[4] | (l[5] << 16), l[6] | (l[7] << 16));
}
// gelu two values, split each into hi/lo bf16, pack pairs
__device__ __forceinline__ void gelu_split2(float x0, float x1, uint32_t& hp, uint32_t& lp) {
    float g0 = gelu_exact(x0), g1 = gelu_exact(x1);
    __nv_bfloat16 b0 = __float2bfloat16_rn(g0), b1 = __float2bfloat16_rn(g1);
    hp = (uint32_t)__bfloat16_as_ushort(b0) | ((uint32_t)__bfloat16_as_ushort(b1) << 16);
    __nv_bfloat16 l0 = __float2bfloat16_rn(g0 - __bfloat162float(b0));
    __nv_bfloat16 l1 = __float2bfloat16_rn(g1 - __bfloat162float(b1));
    lp = (uint32_t)__bfloat16_as_ushort(l0) | ((uint32_t)__bfloat16_as_ushort(l1) << 16);
}

// ---------------- init ----------------
__global__ void init_kernel() {
    int i = threadIdx.x;
    if (i < E_EXP) { g_cnt[i] = 0; g_psum[i] = 0.f; }
    if (i == 0)    { g_zsum = 0.f; }
}

__global__ void zero_out_kernel(float* __restrict__ out) {
    size_t i = ((size_t)blockIdx.x * blockDim.x + threadIdx.x) * 4;
    *(float4*)(out + i) = make_float4(0.f, 0.f, 0.f, 0.f);
}

// ---------------- router ----------------
__global__ void router_kernel(const float* __restrict__ x,
                              const float* __restrict__ rw) {
    __shared__ float sx[D_DIM];
    __shared__ float slog[E_EXP];
    int t = blockIdx.x;
    const float* xr = x + (size_t)t * D_DIM;
    for (int i = threadIdx.x; i < D_DIM; i += blockDim.x) sx[i] = xr[i];
    __syncthreads();

    int w = threadIdx.x >> 5, lane = threadIdx.x & 31;
    float acc = 0.f;
    const float* we = rw + w * D_DIM;
    for (int i = lane; i < D_DIM; i += 32) acc += sx[i] * we[i];
    #pragma unroll
    for (int o = 16; o; o >>= 1) acc += __shfl_xor_sync(0xffffffffu, acc, o);
    if (lane == 0) slog[w] = acc;
    __syncthreads();

    if (threadIdx.x == 0) {
        float l[E_EXP], p[E_EXP];
        float m = -1e30f;
        #pragma unroll
        for (int e = 0; e < E_EXP; e++) { l[e] = slog[e]; m = fmaxf(m, l[e]); }
        float s = 0.f;
        #pragma unroll
        for (int e = 0; e < E_EXP; e++) { p[e] = expf(l[e] - m); s += p[e]; }
        float inv_s = 1.f / s;
        #pragma unroll
        for (int e = 0; e < E_EXP; e++) p[e] *= inv_s;
        float lse = m + logf(s);
        atomicAdd(&g_zsum, lse * lse);
        #pragma unroll
        for (int e = 0; e < E_EXP; e++) atomicAdd(&g_psum[e], p[e]);

        int i0 = 0; float p0 = p[0];
        #pragma unroll
        for (int e = 1; e < E_EXP; e++) if (p[e] > p0) { p0 = p[e]; i0 = e; }
        int i1 = -1; float p1 = -1.f;
        #pragma unroll
        for (int e = 0; e < E_EXP; e++) {
            if (e == i0) continue;
            if (p[e] > p1) { p1 = p[e]; i1 = e; }
        }
        float invn = 1.f / (p0 + p1);
        g_sel[2 * t + 0] = i0; g_wsel[2 * t + 0] = p0 * invn;
        g_sel[2 * t + 1] = i1; g_wsel[2 * t + 1] = p1 * invn;
        atomicAdd(&g_cnt[i0], 1);
        atomicAdd(&g_cnt[i1], 1);
    }
}

__global__ void scan_kernel() {
    if (threadIdx.x == 0) {
        int o = 0;
        for (int e = 0; e < E_EXP; e++) { g_base[e] = o; g_cursor[e] = o; o += g_cnt[e]; }
    }
}

__global__ void place_kernel() {
    int t = blockIdx.x * blockDim.x + threadIdx.x;
    if (t >= T_TOK) return;
    #pragma unroll
    for (int k = 0; k < TOPK; k++) {
        int e = g_sel[2 * t + k];
        int pos = atomicAdd(&g_cursor[e], 1);
        g_rowtok[pos] = t;
        g_roww[pos] = g_wsel[2 * t + k];
        g_rowloc[2 * t + k] = pos;
    }
}

// ---------------- pre-splits ----------------
__global__ void convert_x_kernel(const float* __restrict__ x) {
    size_t i = ((size_t)blockIdx.x * blockDim.x + threadIdx.x) * 8;
    float4 v0 = *(const float4*)(x + i);
    float4 v1 = *(const float4*)(x + i + 4);
    uint4 hi, lo;
    split8(v0, v1, hi, lo);
    *(uint4*)(g_x_hi + i) = hi;
    *(uint4*)(g_x_lo + i) = lo;
}

// w1 [D][EFF] -> wt rows [e*FF+ff][d], bf16 hi/lo
__global__ void transpose_w1_kernel(const float* __restrict__ w1) {
    __shared__ float tile[32][33];
    int n0 = blockIdx.x * 32, k0 = blockIdx.y * 32;
    int tx = threadIdx.x, ty = threadIdx.y;
    #pragma unroll
    for (int i = 0; i < 4; i++)
        tile[ty + i * 8][tx] = w1[(size_t)(k0 + ty + i * 8) * EFF + n0 + tx];
    __syncthreads();
    #pragma unroll
    for (int i = 0; i < 4; i++) {
        float v = tile[tx][ty + i * 8];
        __nv_bfloat16 h = __float2bfloat16_rn(v);
        size_t o = (size_t)(n0 + ty + i * 8) * D_DIM + k0 + tx;
        g_wt_hi[o] = h;
        g_wt_lo[o] = __float2bfloat16_rn(v - __bfloat162float(h));
    }
}

// w2 [e*FF+k][D] -> wt rows [e*D+d][ff], bf16 hi/lo (runs AFTER gemm1)
__global__ void transpose_w2_kernel(const float* __restrict__ w2) {
    __shared__ float tile[32][33];
    int c0 = blockIdx.x * 32, r0 = blockIdx.y * 32;
    int tx = threadIdx.x, ty = threadIdx.y;
    #pragma unroll
    for (int i = 0; i < 4; i++)
        tile[ty + i * 8][tx] = w2[(size_t)(r0 + ty + i * 8) * D_DIM + c0 + tx];
    __syncthreads();
    int e = r0 >> 11, kl = r0 & (FF_DIM - 1);
    #pragma unroll
    for (int i = 0; i < 4; i++) {
        float v = tile[tx][ty + i * 8];
        __nv_bfloat16 h = __float2bfloat16_rn(v);
        size_t o = (size_t)(e * D_DIM + c0 + ty + i * 8) * FF_DIM + kl + tx;
        g_wt_hi[o] = h;
        g_wt_lo[o] = __float2bfloat16_rn(v - __bfloat162float(h));
    }
}

// ================= MMA GEMM core (pre-split bf16 sources; pure copy hot loop) ====
// IS_GEMM1: A = gather(g_x via rowtok) [K=D], B = wt(w1t), epilogue gelu -> g_h hi/lo
// else:     A = g_h rows [K=FF],        B = wt(w2t), epilogue weighted atomicAdd -> out
template <int KTOT, bool IS_GEMM1>
__global__ void __launch_bounds__(256, 1)
gemm_mma(float* __restrict__ out) {
    __shared__ __align__(16) char smem[2 * STAGE_SZ];   // 32 KB

    const int N_TOTAL = IS_GEMM1 ? FF_DIM : D_DIM;

    int e = blockIdx.z;
    int n_e = g_cnt[e], base = g_base[e];
    int m0 = blockIdx.y * BM;
    if (m0 >= n_e) return;
    int n0 = blockIdx.x * BN;

    int tid = threadIdx.x, lane = tid & 31, wid = tid >> 5;
    uint32_t sb = smem_u32(smem);

    int crow = tid >> 1, cseg = tid & 1;
    const __nv_bfloat16 *pah, *pal;
    if (IS_GEMM1) {
        int arow_g = m0 + crow;
        int tok = (arow_g < n_e) ? g_rowtok[base + arow_g] : 0;
        size_t ao = (size_t)tok * KTOT + cseg * 8;
        pah = g_x_hi + ao; pal = g_x_lo + ao;
    } else {
        size_t ao = (size_t)(base + m0 + crow) * KTOT + cseg * 8;
        pah = g_h_hi + ao; pal = g_h_lo + ao;
    }
    size_t bo = ((size_t)e * N_TOTAL + n0 + crow) * KTOT + cseg * 8;
    const __nv_bfloat16* pbh = g_wt_hi + bo;
    const __nv_bfloat16* pbl = g_wt_lo + bo;
    uint32_t wdst = swz2(crow, cseg);

    const int NCH = KTOT / BK;

    uint4 rah, ral, rbh, rbl;
    auto loadc = [&](int ch) {
        int k0 = ch * BK;
        rah = *(const uint4*)(pah + k0);
        ral = *(const uint4*)(pal + k0);
        rbh = *(const uint4*)(pbh + k0);
        rbl = *(const uint4*)(pbl + k0);
    };
    auto storec = [&](int s) {
        char* p = smem + s * STAGE_SZ + wdst;
        *(uint4*)(p)              = rah;
        *(uint4*)(p + PART_B)     = ral;
        *(uint4*)(p + 2 * PART_B) = rbh;
        *(uint4*)(p + 3 * PART_B) = rbl;
    };

    loadc(0);
    storec(0);
    loadc(1);
    __syncthreads();

    int warp_m = (wid & 1) * 64, warp_n = (wid >> 1) * 32;

    float acc[4][4][4];
    #pragma unroll
    for (int i = 0; i < 4; i++)
        #pragma unroll
        for (int j = 0; j < 4; j++)
            #pragma unroll
            for (int q = 0; q < 4; q++) acc[i][j][q] = 0.f;

    uint32_t aphys = swz2(warp_m + (lane & 15), lane >> 4);
    uint32_t bphys = swz2(warp_n + (lane & 7) + ((lane & 16) ? 8 : 0), (lane >> 3) & 1);

    for (int ch = 0; ch < NCH; ch++) {
        if (ch + 1 < NCH) storec((ch + 1) & 1);
        if (ch + 2 < NCH) loadc(ch + 2);

        uint32_t st = sb + (ch & 1) * STAGE_SZ;
        uint32_t ah[4][4], al[4][4], bh[4][2], bl[4][2];
        #pragma unroll
        for (int mi = 0; mi < 4; mi++) {
            ldsm4(ah[mi], st + aphys + mi * 512);
            ldsm4(al[mi], st + PART_B + aphys + mi * 512);
        }
        #pragma unroll
        for (int ng = 0; ng < 2; ng++) {
            uint32_t r[4];
            ldsm4(r, st + 2 * PART_B + bphys + ng * 512);
            bh[ng * 2][0] = r[0]; bh[ng * 2][1] = r[1];
            bh[ng * 2 + 1][0] = r[2]; bh[ng * 2 + 1][1] = r[3];
            ldsm4(r, st + 3 * PART_B + bphys + ng * 512);
            bl[ng * 2][0] = r[0]; bl[ng * 2][1] = r[1];
            bl[ng * 2 + 1][0] = r[2]; bl[ng * 2 + 1][1] = r[3];
        }
        #pragma unroll
        for (int mi = 0; mi < 4; mi++)
            #pragma unroll
            for (int ni = 0; ni < 4; ni++) mma16816(acc[mi][ni], ah[mi], bh[ni]);
        #pragma unroll
        for (int mi = 0; mi < 4; mi++)
            #pragma unroll
            for (int ni = 0; ni < 4; ni++) mma16816(acc[mi][ni], ah[mi], bl[ni]);
        #pragma unroll
        for (int mi = 0; mi < 4; mi++)
            #pragma unroll
            for (int ni = 0; ni < 4; ni++) mma16816(acc[mi][ni], al[mi], bh[ni]);
        __syncthreads();
    }

    // ---------------- epilogue ----------------
    #pragma unroll
    for (int mi = 0; mi < 4; mi++) {
        int gr0 = m0 + warp_m + mi * 16 + (lane >> 2);
        int gr1 = gr0 + 8;
        bool v0 = gr0 < n_e, v1 = gr1 < n_e;
        int tok0 = 0, tok1 = 0; float wgt0 = 0.f, wgt1 = 0.f;
        if (!IS_GEMM1) {
            if (v0) { tok0 = g_rowtok[base + gr0]; wgt0 = g_roww[base + gr0]; }
            if (v1) { tok1 = g_rowtok[base + gr1]; wgt1 = g_roww[base + gr1]; }
        }
        #pragma unroll
        for (int ni = 0; ni < 4; ni++) {
            int c_col = n0 + warp_n + ni * 8 + (lane & 3) * 2;
            float* a4 = acc[mi][ni];
            if (IS_GEMM1) {
                if (v0) {
                    uint32_t hp, lp;
                    gelu_split2(a4[0], a4[1], hp, lp);
                    size_t o = (size_t)(base + gr0) * FF_DIM + c_col;
                    *(uint32_t*)(g_h_hi + o) = hp;
                    *(uint32_t*)(g_h_lo + o) = lp;
                }
                if (v1) {
                    uint32_t hp, lp;
                    gelu_split2(a4[2], a4[3], hp, lp);
                    size_t o = (size_t)(base + gr1) * FF_DIM + c_col;
                    *(uint32_t*)(g_h_hi + o) = hp;
                    *(uint32_t*)(g_h_lo + o) = lp;
                }
            } else {
                if (v0) {
                    float* op = out + (size_t)tok0 * D_DIM + c_col;
                    atomicAdd(op,     wgt0 * a4[0]);
                    atomicAdd(op + 1, wgt0 * a4[1]);
                }
                if (v1) {
                    float* op = out + (size_t)tok1 * D_DIM + c_col;
                    atomicAdd(op,     wgt1 * a4[2]);
                    atomicAdd(op + 1, wgt1 * a4[3]);
                }
            }
        }
    }
}

// ---------------- finalize scalars ----------------
__global__ void finalize_kernel(float* __restrict__ out, int out_size) {
    if (threadIdx.x == 0) {
        float z = g_zsum / (float)T_TOK;
        float lb = 0.f;
        for (int e = 0; e < E_EXP; e++) {
            float f_i = (float)g_cnt[e] / (float)(T_TOK * TOPK);
            float p_i = g_psum[e] / (float)T_TOK;
            lb += f_i * p_i;
        }
        lb *= (float)E_EXP;
        out[out_size - 2] = z;
        out[out_size - 1] = lb;
    }
}

// ---------------- launch ----------------
extern "C" void kernel_launch(void* const* d_in, const int* in_sizes, int n_in,
                              void* d_out, int out_size) {
    const float* x  = (const float*)d_in[0];
    const float* rw = (const float*)d_in[1];
    const float* w1 = (const float*)d_in[2];
    const float* w2 = (const float*)d_in[3];
    float* out = (float*)d_out;

    init_kernel<<<1, 32>>>();
    router_kernel<<<T_TOK, 256>>>(x, rw);
    scan_kernel<<<1, 1>>>();
    place_kernel<<<(T_TOK + 255) / 256, 256>>>();

    convert_x_kernel<<<(T_TOK * D_DIM / 8) / 256, 256>>>(x);
    transpose_w1_kernel<<<dim3(EFF / 32, D_DIM / 32), dim3(32, 8)>>>(w1);

    // GEMM1 (consumes wt as w1t, writes g_h hi/lo)
    gemm_mma<D_DIM, true><<<dim3(FF_DIM / BN, T_TOK / BM, E_EXP), 256>>>(out);

    // reuse wt for w2t, then GEMM2 with fused weighted scatter into out
    transpose_w2_kernel<<<dim3(D_DIM / 32, EFF / 32), dim3(32, 8)>>>(w2);
    zero_out_kernel<<<(T_TOK * D_DIM / 4) / 256, 256>>>(out);
    gemm_mma<FF_DIM, false><<<dim3(D_DIM / BN, T_TOK / BM, E_EXP), 256>>>(out);

    finalize_kernel<<<1, 1>>>(out, out_size);
}

// round 13
// speedup vs baseline: 2.2053x; 1.0319x over previous
#include <cuda_runtime.h>
#include <cuda_bf16.h>
#include <math.h>
#include <stdint.h>

// ---------------- problem constants ----------------
#define T_TOK   8192
#define D_DIM   1024
#define E_EXP   8
#define TOPK    2
#define FF_DIM  2048
#define EFF     (E_EXP * FF_DIM)
#define NROWS   (T_TOK * TOPK)      // 16384
#define HPAD    128

// MMA GEMM tiling
#define BM 128
#define BN 128
#define BK 16
#define PART_B   4096                // 128 rows * 32 B of bf16 halves
#define STAGE_SZ (4 * PART_B)        // Ahi | Alo | Bhi | Blo = 16 KB
#define NSTAGE   3                   // 48 KB static shared (no opt-in needed)

// ---------------- device scratch (~236 MB; no symbol crosses a launch) ----------------
__device__ __nv_bfloat16 g_x_hi[(size_t)T_TOK * D_DIM];
__device__ __nv_bfloat16 g_x_lo[(size_t)T_TOK * D_DIM];
__device__ __nv_bfloat16 g_wt_hi[(size_t)EFF * D_DIM];             // w1t, then w2t
__device__ __nv_bfloat16 g_wt_lo[(size_t)EFF * D_DIM];
__device__ __nv_bfloat16 g_h_hi[(size_t)(NROWS + HPAD) * FF_DIM];
__device__ __nv_bfloat16 g_h_lo[(size_t)(NROWS + HPAD) * FF_DIM];
__device__ int   g_cnt[E_EXP];
__device__ int   g_base[E_EXP];
__device__ int   g_cursor[E_EXP];
__device__ int   g_rowtok[NROWS];
__device__ float g_roww[NROWS];
__device__ int   g_rowloc[NROWS];
__device__ int   g_sel[NROWS];
__device__ float g_wsel[NROWS];
__device__ float g_zsum;
__device__ float g_psum[E_EXP];

// ---------------- helpers ----------------
__device__ __forceinline__ uint32_t smem_u32(const void* p) {
    uint32_t a;
    asm("{ .reg .u64 t; cvta.to.shared.u64 t, %1; cvt.u32.u64 %0, t; }" : "=r"(a) : "l"(p));
    return a;
}
__device__ __forceinline__ void cpa16(uint32_t dst, const void* src) {
    asm volatile("cp.async.cg.shared.global [%0], [%1], 16;" :: "r"(dst), "l"(src) : "memory");
}
__device__ __forceinline__ void cp_commit() { asm volatile("cp.async.commit_group;" ::: "memory"); }
__device__ __forceinline__ void cp_wait2()  { asm volatile("cp.async.wait_group 2;" ::: "memory"); }

__device__ __forceinline__ void ldsm4(uint32_t* r, uint32_t addr) {
    asm volatile("ldmatrix.sync.aligned.m8n8.x4.shared.b16 {%0,%1,%2,%3}, [%4];"
                 : "=r"(r[0]), "=r"(r[1]), "=r"(r[2]), "=r"(r[3]) : "r"(addr));
}
__device__ __forceinline__ void mma16816(float* c, const uint32_t* a, const uint32_t* b) {
    asm volatile("mma.sync.aligned.m16n8k16.row.col.f32.bf16.bf16.f32 "
                 "{%0,%1,%2,%3}, {%4,%5,%6,%7}, {%8,%9}, {%0,%1,%2,%3};"
                 : "+f"(c[0]), "+f"(c[1]), "+f"(c[2]), "+f"(c[3])
                 : "r"(a[0]), "r"(a[1]), "r"(a[2]), "r"(a[3]), "r"(b[0]), "r"(b[1]));
}
__device__ __forceinline__ float gelu_exact(float v) {
    return 0.5f * v * (1.0f + erff(v * 0.70710678118654752f));
}
__device__ __forceinline__ uint32_t swz2(int r, int s) {
    return (uint32_t)(r * 32 + (((s ^ r ^ (r >> 2)) & 1) << 4));
}
__device__ __forceinline__ void split8(float4 v0, float4 v1, uint4& hi, uint4& lo) {
    float f[8] = {v0.x, v0.y, v0.z, v0.w, v1.x, v1.y, v1.z, v1.w};
    uint32_t h[8], l[8];
    #pragma unroll
    for (int i = 0; i < 8; i++) {
        __nv_bfloat16 b = __float2bfloat16_rn(f[i]);
        h[i] = (uint32_t)__bfloat16_as_ushort(b);
        l[i] = (uint32_t)__bfloat16_as_ushort(__float2bfloat16_rn(f[i] - __bfloat162float(b)));
    }
    hi = make_uint4(h[0] | (h[1] << 16), h[2] | (h[3] << 16), h[4] | (h[5] << 16), h[6] | (h[7] << 16));
    lo = make_uint4(l[0] | (l[1] << 16), l[2] | (l[3] << 16), l[4] | (l[5] << 16), l[6] | (l[7] << 16));
}
__device__ __forceinline__ void gelu_split2(float x0, float x1, uint32_t& hp, uint32_t& lp) {
    float g0 = gelu_exact(x0), g1 = gelu_exact(x1);
    __nv_bfloat16 b0 = __float2bfloat16_rn(g0), b1 = __float2bfloat16_rn(g1);
    hp = (uint32_t)__bfloat16_as_ushort(b0) | ((uint32_t)__bfloat16_as_ushort(b1) << 16);
    __nv_bfloat16 l0 = __float2bfloat16_rn(g0 - __bfloat162float(b0));
    __nv_bfloat16 l1 = __float2bfloat16_rn(g1 - __bfloat162float(b1));
    lp = (uint32_t)__bfloat16_as_ushort(l0) | ((uint32_t)__bfloat16_as_ushort(l1) << 16);
}

// ---------------- init ----------------
__global__ void init_kernel() {
    int i = threadIdx.x;
    if (i < E_EXP) { g_cnt[i] = 0; g_psum[i] = 0.f; }
    if (i == 0)    { g_zsum = 0.f; }
}

__global__ void zero_out_kernel(float* __restrict__ out) {
    size_t i = ((size_t)blockIdx.x * blockDim.x + threadIdx.x) * 4;
    *(float4*)(out + i) = make_float4(0.f, 0.f, 0.f, 0.f);
}

// ---------------- router ----------------
__global__ void router_kernel(const float* __restrict__ x,
                              const float* __restrict__ rw) {
    __shared__ float sx[D_DIM];
    __shared__ float slog[E_EXP];
    int t = blockIdx.x;
    const float* xr = x + (size_t)t * D_DIM;
    for (int i = threadIdx.x; i < D_DIM; i += blockDim.x) sx[i] = xr[i];
    __syncthreads();

    int w = threadIdx.x >> 5, lane = threadIdx.x & 31;
    float acc = 0.f;
    const float* we = rw + w * D_DIM;
    for (int i = lane; i < D_DIM; i += 32) acc += sx[i] * we[i];
    #pragma unroll
    for (int o = 16; o; o >>= 1) acc += __shfl_xor_sync(0xffffffffu, acc, o);
    if (lane == 0) slog[w] = acc;
    __syncthreads();

    if (threadIdx.x == 0) {
        float l[E_EXP], p[E_EXP];
        float m = -1e30f;
        #pragma unroll
        for (int e = 0; e < E_EXP; e++) { l[e] = slog[e]; m = fmaxf(m, l[e]); }
        float s = 0.f;
        #pragma unroll
        for (int e = 0; e < E_EXP; e++) { p[e] = expf(l[e] - m); s += p[e]; }
        float inv_s = 1.f / s;
        #pragma unroll
        for (int e = 0; e < E_EXP; e++) p[e] *= inv_s;
        float lse = m + logf(s);
        atomicAdd(&g_zsum, lse * lse);
        #pragma unroll
        for (int e = 0; e < E_EXP; e++) atomicAdd(&g_psum[e], p[e]);

        int i0 = 0; float p0 = p[0];
        #pragma unroll
        for (int e = 1; e < E_EXP; e++) if (p[e] > p0) { p0 = p[e]; i0 = e; }
        int i1 = -1; float p1 = -1.f;
        #pragma unroll
        for (int e = 0; e < E_EXP; e++) {
            if (e == i0) continue;
            if (p[e] > p1) { p1 = p[e]; i1 = e; }
        }
        float invn = 1.f / (p0 + p1);
        g_sel[2 * t + 0] = i0; g_wsel[2 * t + 0] = p0 * invn;
        g_sel[2 * t + 1] = i1; g_wsel[2 * t + 1] = p1 * invn;
        atomicAdd(&g_cnt[i0], 1);
        atomicAdd(&g_cnt[i1], 1);
    }
}

__global__ void scan_kernel() {
    if (threadIdx.x == 0) {
        int o = 0;
        for (int e = 0; e < E_EXP; e++) { g_base[e] = o; g_cursor[e] = o; o += g_cnt[e]; }
    }
}

__global__ void place_kernel() {
    int t = blockIdx.x * blockDim.x + threadIdx.x;
    if (t >= T_TOK) return;
    #pragma unroll
    for (int k = 0; k < TOPK; k++) {
        int e = g_sel[2 * t + k];
        int pos = atomicAdd(&g_cursor[e], 1);
        g_rowtok[pos] = t;
        g_roww[pos] = g_wsel[2 * t + k];
        g_rowloc[2 * t + k] = pos;
    }
}

// ---------------- pre-splits ----------------
__global__ void convert_x_kernel(const float* __restrict__ x) {
    size_t i = ((size_t)blockIdx.x * blockDim.x + threadIdx.x) * 8;
    float4 v0 = *(const float4*)(x + i);
    float4 v1 = *(const float4*)(x + i + 4);
    uint4 hi, lo;
    split8(v0, v1, hi, lo);
    *(uint4*)(g_x_hi + i) = hi;
    *(uint4*)(g_x_lo + i) = lo;
}

// w1 [D][EFF] -> wt rows [e*FF+ff][d], bf16 hi/lo
__global__ void transpose_w1_kernel(const float* __restrict__ w1) {
    __shared__ float tile[32][33];
    int n0 = blockIdx.x * 32, k0 = blockIdx.y * 32;
    int tx = threadIdx.x, ty = threadIdx.y;
    #pragma unroll
    for (int i = 0; i < 4; i++)
        tile[ty + i * 8][tx] = w1[(size_t)(k0 + ty + i * 8) * EFF + n0 + tx];
    __syncthreads();
    #pragma unroll
    for (int i = 0; i < 4; i++) {
        float v = tile[tx][ty + i * 8];
        __nv_bfloat16 h = __float2bfloat16_rn(v);
        size_t o = (size_t)(n0 + ty + i * 8) * D_DIM + k0 + tx;
        g_wt_hi[o] = h;
        g_wt_lo[o] = __float2bfloat16_rn(v - __bfloat162float(h));
    }
}

// w2 [e*FF+k][D] -> wt rows [e*D+d][ff], bf16 hi/lo (runs AFTER gemm1)
__global__ void transpose_w2_kernel(const float* __restrict__ w2) {
    __shared__ float tile[32][33];
    int c0 = blockIdx.x * 32, r0 = blockIdx.y * 32;
    int tx = threadIdx.x, ty = threadIdx.y;
    #pragma unroll
    for (int i = 0; i < 4; i++)
        tile[ty + i * 8][tx] = w2[(size_t)(r0 + ty + i * 8) * D_DIM + c0 + tx];
    __syncthreads();
    int e = r0 >> 11, kl = r0 & (FF_DIM - 1);
    #pragma unroll
    for (int i = 0; i < 4; i++) {
        float v = tile[tx][ty + i * 8];
        __nv_bfloat16 h = __float2bfloat16_rn(v);
        size_t o = (size_t)(e * D_DIM + c0 + ty + i * 8) * FF_DIM + kl + tx;
        g_wt_hi[o] = h;
        g_wt_lo[o] = __float2bfloat16_rn(v - __bfloat162float(h));
    }
}

// ================= MMA GEMM core (cp.async 3-stage; LDSM/MMA interleave) ========
// IS_GEMM1: A = gather(g_x via rowtok) [K=D], B = wt(w1t), epilogue gelu -> g_h hi/lo
// else:     A = g_h rows [K=FF],        B = wt(w2t), epilogue weighted atomicAdd -> out
template <int KTOT, bool IS_GEMM1>
__global__ void __launch_bounds__(256, 1)
gemm_mma(float* __restrict__ out) {
    __shared__ __align__(16) char smem[NSTAGE * STAGE_SZ];   // 48 KB static

    const int N_TOTAL = IS_GEMM1 ? FF_DIM : D_DIM;

    int e = blockIdx.z;
    int n_e = g_cnt[e], base = g_base[e];
    int m0 = blockIdx.y * BM;
    if (m0 >= n_e) return;
    int n0 = blockIdx.x * BN;

    int tid = threadIdx.x, lane = tid & 31, wid = tid >> 5;
    uint32_t sb = smem_u32(smem);

    int crow = tid >> 1, cseg = tid & 1;
    const __nv_bfloat16 *pah, *pal;
    if (IS_GEMM1) {
        int arow_g = m0 + crow;
        int tok = (arow_g < n_e) ? g_rowtok[base + arow_g] : 0;
        size_t ao = (size_t)tok * KTOT + cseg * 8;
        pah = g_x_hi + ao; pal = g_x_lo + ao;
    } else {
        size_t ao = (size_t)(base + m0 + crow) * KTOT + cseg * 8;
        pah = g_h_hi + ao; pal = g_h_lo + ao;
    }
    size_t bo = ((size_t)e * N_TOTAL + n0 + crow) * KTOT + cseg * 8;
    const __nv_bfloat16* pbh = g_wt_hi + bo;
    const __nv_bfloat16* pbl = g_wt_lo + bo;
    uint32_t wdst = swz2(crow, cseg);

    const int NCH = KTOT / BK;

    auto issue = [&](int ch) {
        uint32_t d = sb + (ch % NSTAGE) * STAGE_SZ + wdst;
        int k0 = ch * BK;
        cpa16(d,              pah + k0);
        cpa16(d + PART_B,     pal + k0);
        cpa16(d + 2 * PART_B, pbh + k0);
        cpa16(d + 3 * PART_B, pbl + k0);
    };

    issue(0); cp_commit();
    issue(1); cp_commit();
    issue(2); cp_commit();

    int warp_m = (wid & 1) * 64, warp_n = (wid >> 1) * 32;

    float acc[4][4][4];
    #pragma unroll
    for (int i = 0; i < 4; i++)
        #pragma unroll
        for (int j = 0; j < 4; j++)
            #pragma unroll
            for (int q = 0; q < 4; q++) acc[i][j][q] = 0.f;

    uint32_t aphys = swz2(warp_m + (lane & 15), lane >> 4);
    uint32_t bphys = swz2(warp_n + (lane & 7) + ((lane & 16) ? 8 : 0), (lane >> 3) & 1);

    for (int ch = 0; ch < NCH; ch++) {
        cp_wait2();
        __syncthreads();

        uint32_t st = sb + (ch % NSTAGE) * STAGE_SZ;
        uint32_t ah[4][4], al[4][4], bh[4][2], bl[4][2];

        // hi frags first
        #pragma unroll
        for (int mi = 0; mi < 4; mi++) ldsm4(ah[mi], st + aphys + mi * 512);
        #pragma unroll
        for (int ng = 0; ng < 2; ng++) {
            uint32_t r[4];
            ldsm4(r, st + 2 * PART_B + bphys + ng * 512);
            bh[ng * 2][0] = r[0]; bh[ng * 2][1] = r[1];
            bh[ng * 2 + 1][0] = r[2]; bh[ng * 2 + 1][1] = r[3];
        }
        // hh MMAs with lo-frag LDSMs interleaved (asm order preserved)
        #pragma unroll
        for (int mi = 0; mi < 4; mi++) {
            ldsm4(al[mi], st + PART_B + aphys + mi * 512);
            #pragma unroll
            for (int ni = 0; ni < 4; ni++) mma16816(acc[mi][ni], ah[mi], bh[ni]);
        }
        #pragma unroll
        for (int ng = 0; ng < 2; ng++) {
            uint32_t r[4];
            ldsm4(r, st + 3 * PART_B + bphys + ng * 512);
            bl[ng * 2][0] = r[0]; bl[ng * 2][1] = r[1];
            bl[ng * 2 + 1][0] = r[2]; bl[ng * 2 + 1][1] = r[3];
        }
        #pragma unroll
        for (int mi = 0; mi < 4; mi++)
            #pragma unroll
            for (int ni = 0; ni < 4; ni++) mma16816(acc[mi][ni], ah[mi], bl[ni]);
        #pragma unroll
        for (int mi = 0; mi < 4; mi++)
            #pragma unroll
            for (int ni = 0; ni < 4; ni++) mma16816(acc[mi][ni], al[mi], bh[ni]);

        __syncthreads();
        if (ch + 3 < NCH) issue(ch + 3);
        cp_commit();
    }

    // ---------------- epilogue ----------------
    #pragma unroll
    for (int mi = 0; mi < 4; mi++) {
        int gr0 = m0 + warp_m + mi * 16 + (lane >> 2);
        int gr1 = gr0 + 8;
        bool v0 = gr0 < n_e, v1 = gr1 < n_e;
        int tok0 = 0, tok1 = 0; float wgt0 = 0.f, wgt1 = 0.f;
        if (!IS_GEMM1) {
            if (v0) { tok0 = g_rowtok[base + gr0]; wgt0 = g_roww[base + gr0]; }
            if (v1) { tok1 = g_rowtok[base + gr1]; wgt1 = g_roww[base + gr1]; }
        }
        #pragma unroll
        for (int ni = 0; ni < 4; ni++) {
            int c_col = n0 + warp_n + ni * 8 + (lane & 3) * 2;
            float* a4 = acc[mi][ni];
            if (IS_GEMM1) {
                if (v0) {
                    uint32_t hp, lp;
                    gelu_split2(a4[0], a4[1], hp, lp);
                    size_t o = (size_t)(base + gr0) * FF_DIM + c_col;
                    *(uint32_t*)(g_h_hi + o) = hp;
                    *(uint32_t*)(g_h_lo + o) = lp;
                }
                if (v1) {
                    uint32_t hp, lp;
                    gelu_split2(a4[2], a4[3], hp, lp);
                    size_t o = (size_t)(base + gr1) * FF_DIM + c_col;
                    *(uint32_t*)(g_h_hi + o) = hp;
                    *(uint32_t*)(g_h_lo + o) = lp;
                }
            } else {
                if (v0) {
                    float* op = out + (size_t)tok0 * D_DIM + c_col;
                    atomicAdd(op,     wgt0 * a4[0]);
                    atomicAdd(op + 1, wgt0 * a4[1]);
                }
                if (v1) {
                    float* op = out + (size_t)tok1 * D_DIM + c_col;
                    atomicAdd(op,     wgt1 * a4[2]);
                    atomicAdd(op + 1, wgt1 * a4[3]);
                }
            }
        }
    }
}

// ---------------- finalize scalars ----------------
__global__ void finalize_kernel(float* __restrict__ out, int out_size) {
    if (threadIdx.x == 0) {
        float z = g_zsum / (float)T_TOK;
        float lb = 0.f;
        for (int e = 0; e < E_EXP; e++) {
            float f_i = (float)g_cnt[e] / (float)(T_TOK * TOPK);
            float p_i = g_psum[e] / (float)T_TOK;
            lb += f_i * p_i;
        }
        lb *= (float)E_EXP;
        out[out_size - 2] = z;
        out[out_size - 1] = lb;
    }
}

// ---------------- launch ----------------
extern "C" void kernel_launch(void* const* d_in, const int* in_sizes, int n_in,
                              void* d_out, int out_size) {
    const float* x  = (const float*)d_in[0];
    const float* rw = (const float*)d_in[1];
    const float* w1 = (const float*)d_in[2];
    const float* w2 = (const float*)d_in[3];
    float* out = (float*)d_out;

    init_kernel<<<1, 32>>>();
    router_kernel<<<T_TOK, 256>>>(x, rw);
    scan_kernel<<<1, 1>>>();
    place_kernel<<<(T_TOK + 255) / 256, 256>>>();

    convert_x_kernel<<<(T_TOK * D_DIM / 8) / 256, 256>>>(x);
    transpose_w1_kernel<<<dim3(EFF / 32, D_DIM / 32), dim3(32, 8)>>>(w1);

    // GEMM1 (consumes wt as w1t, writes g_h hi/lo)
    gemm_mma<D_DIM, true><<<dim3(FF_DIM / BN, T_TOK / BM, E_EXP), 256>>>(out);

    // reuse wt for w2t, then GEMM2 with fused weighted scatter into out
    transpose_w2_kernel<<<dim3(D_DIM / 32, EFF / 32), dim3(32, 8)>>>(w2);
    zero_out_kernel<<<(T_TOK * D_DIM / 4) / 256, 256>>>(out);
    gemm_mma<FF_DIM, false><<<dim3(D_DIM / BN, T_TOK / BM, E_EXP), 256>>>(out);

    finalize_kernel<<<1, 1>>>(out, out_size);
}

// round 15
// speedup vs baseline: 2.9989x; 1.3598x over previous
#include <cuda_runtime.h>
#include <cuda_fp16.h>
#include <math.h>
#include <stdint.h>

// ---------------- problem constants ----------------
#define T_TOK   8192
#define D_DIM   1024
#define E_EXP   8
#define TOPK    2
#define FF_DIM  2048
#define EFF     (E_EXP * FF_DIM)
#define NROWS   (T_TOK * TOPK)      // 16384
#define HPAD    128

// MMA GEMM tiling
#define BM 128
#define BN 128
#define BK 16
#define PART_B   4096                // 128 rows * 32 B of halves
#define STAGE_SZ (3 * PART_B)        // A | Bhi | Blo = 12 KB
#define NSTAGE   3                   // 36 KB static shared

// ---------------- device scratch (~152 MB; no symbol crosses a launch) ----------------
__device__ __half g_x_h[(size_t)T_TOK * D_DIM];                 // 16.8 MB (single fp16)
__device__ __half g_wt_hi[(size_t)EFF * D_DIM];                 // 33.5 MB (w1t, then w2t)
__device__ __half g_wt_lo[(size_t)EFF * D_DIM];                 // 33.5 MB
__device__ __half g_h_h[(size_t)(NROWS + HPAD) * FF_DIM];       // 67.6 MB (single fp16)
__device__ int   g_cnt[E_EXP];
__device__ int   g_base[E_EXP];
__device__ int   g_cursor[E_EXP];
__device__ int   g_rowtok[NROWS];
__device__ float g_roww[NROWS];
__device__ int   g_rowloc[NROWS];
__device__ int   g_sel[NROWS];
__device__ float g_wsel[NROWS];
__device__ float g_zsum;
__device__ float g_psum[E_EXP];

// ---------------- helpers ----------------
__device__ __forceinline__ uint32_t smem_u32(const void* p) {
    uint32_t a;
    asm("{ .reg .u64 t; cvta.to.shared.u64 t, %1; cvt.u32.u64 %0, t; }" : "=r"(a) : "l"(p));
    return a;
}
__device__ __forceinline__ void cpa16(uint32_t dst, const void* src) {
    asm volatile("cp.async.cg.shared.global [%0], [%1], 16;" :: "r"(dst), "l"(src) : "memory");
}
__device__ __forceinline__ void cp_commit() { asm volatile("cp.async.commit_group;" ::: "memory"); }
__device__ __forceinline__ void cp_wait2()  { asm volatile("cp.async.wait_group 2;" ::: "memory"); }

__device__ __forceinline__ void ldsm4(uint32_t* r, uint32_t addr) {
    asm volatile("ldmatrix.sync.aligned.m8n8.x4.shared.b16 {%0,%1,%2,%3}, [%4];"
                 : "=r"(r[0]), "=r"(r[1]), "=r"(r[2]), "=r"(r[3]) : "r"(addr));
}
__device__ __forceinline__ void mma16816h(float* c, const uint32_t* a, const uint32_t* b) {
    asm volatile("mma.sync.aligned.m16n8k16.row.col.f32.f16.f16.f32 "
                 "{%0,%1,%2,%3}, {%4,%5,%6,%7}, {%8,%9}, {%0,%1,%2,%3};"
                 : "+f"(c[0]), "+f"(c[1]), "+f"(c[2]), "+f"(c[3])
                 : "r"(a[0]), "r"(a[1]), "r"(a[2]), "r"(a[3]), "r"(b[0]), "r"(b[1]));
}
__device__ __forceinline__ float gelu_exact(float v) {
    return 0.5f * v * (1.0f + erff(v * 0.70710678118654752f));
}
__device__ __forceinline__ uint32_t swz2(int r, int s) {
    return (uint32_t)(r * 32 + (((s ^ r ^ (r >> 2)) & 1) << 4));
}
__device__ __forceinline__ uint32_t pack2hf(float a, float b) {
    __half2 h = __floats2half2_rn(a, b);
    return *(uint32_t*)&h;
}

// ---------------- init ----------------
__global__ void init_kernel() {
    int i = threadIdx.x;
    if (i < E_EXP) { g_cnt[i] = 0; g_psum[i] = 0.f; }
    if (i == 0)    { g_zsum = 0.f; }
}

__global__ void zero_out_kernel(float* __restrict__ out) {
    size_t i = ((size_t)blockIdx.x * blockDim.x + threadIdx.x) * 4;
    *(float4*)(out + i) = make_float4(0.f, 0.f, 0.f, 0.f);
}

// ---------------- router ----------------
__global__ void router_kernel(const float* __restrict__ x,
                              const float* __restrict__ rw) {
    __shared__ float sx[D_DIM];
    __shared__ float slog[E_EXP];
    int t = blockIdx.x;
    const float* xr = x + (size_t)t * D_DIM;
    for (int i = threadIdx.x; i < D_DIM; i += blockDim.x) sx[i] = xr[i];
    __syncthreads();

    int w = threadIdx.x >> 5, lane = threadIdx.x & 31;
    float acc = 0.f;
    const float* we = rw + w * D_DIM;
    for (int i = lane; i < D_DIM; i += 32) acc += sx[i] * we[i];
    #pragma unroll
    for (int o = 16; o; o >>= 1) acc += __shfl_xor_sync(0xffffffffu, acc, o);
    if (lane == 0) slog[w] = acc;
    __syncthreads();

    if (threadIdx.x == 0) {
        float l[E_EXP], p[E_EXP];
        float m = -1e30f;
        #pragma unroll
        for (int e = 0; e < E_EXP; e++) { l[e] = slog[e]; m = fmaxf(m, l[e]); }
        float s = 0.f;
        #pragma unroll
        for (int e = 0; e < E_EXP; e++) { p[e] = expf(l[e] - m); s += p[e]; }
        float inv_s = 1.f / s;
        #pragma unroll
        for (int e = 0; e < E_EXP; e++) p[e] *= inv_s;
        float lse = m + logf(s);
        atomicAdd(&g_zsum, lse * lse);
        #pragma unroll
        for (int e = 0; e < E_EXP; e++) atomicAdd(&g_psum[e], p[e]);

        int i0 = 0; float p0 = p[0];
        #pragma unroll
        for (int e = 1; e < E_EXP; e++) if (p[e] > p0) { p0 = p[e]; i0 = e; }
        int i1 = -1; float p1 = -1.f;
        #pragma unroll
        for (int e = 0; e < E_EXP; e++) {
            if (e == i0) continue;
            if (p[e] > p1) { p1 = p[e]; i1 = e; }
        }
        float invn = 1.f / (p0 + p1);
        g_sel[2 * t + 0] = i0; g_wsel[2 * t + 0] = p0 * invn;
        g_sel[2 * t + 1] = i1; g_wsel[2 * t + 1] = p1 * invn;
        atomicAdd(&g_cnt[i0], 1);
        atomicAdd(&g_cnt[i1], 1);
    }
}

__global__ void scan_kernel() {
    if (threadIdx.x == 0) {
        int o = 0;
        for (int e = 0; e < E_EXP; e++) { g_base[e] = o; g_cursor[e] = o; o += g_cnt[e]; }
    }
}

__global__ void place_kernel() {
    int t = blockIdx.x * blockDim.x + threadIdx.x;
    if (t >= T_TOK) return;
    #pragma unroll
    for (int k = 0; k < TOPK; k++) {
        int e = g_sel[2 * t + k];
        int pos = atomicAdd(&g_cursor[e], 1);
        g_rowtok[pos] = t;
        g_roww[pos] = g_wsel[2 * t + k];
        g_rowloc[2 * t + k] = pos;
    }
}

// ---------------- pre-conversions ----------------
// x -> single fp16
__global__ void convert_x_kernel(const float* __restrict__ x) {
    size_t i = ((size_t)blockIdx.x * blockDim.x + threadIdx.x) * 8;
    float4 v0 = *(const float4*)(x + i);
    float4 v1 = *(const float4*)(x + i + 4);
    uint4 p;
    p.x = pack2hf(v0.x, v0.y);
    p.y = pack2hf(v0.z, v0.w);
    p.z = pack2hf(v1.x, v1.y);
    p.w = pack2hf(v1.z, v1.w);
    *(uint4*)(g_x_h + i) = p;
}

// w1 [D][EFF] -> wt rows [e*FF+ff][d], fp16 hi/lo split
__global__ void transpose_w1_kernel(const float* __restrict__ w1) {
    __shared__ float tile[32][33];
    int n0 = blockIdx.x * 32, k0 = blockIdx.y * 32;
    int tx = threadIdx.x, ty = threadIdx.y;
    #pragma unroll
    for (int i = 0; i < 4; i++)
        tile[ty + i * 8][tx] = w1[(size_t)(k0 + ty + i * 8) * EFF + n0 + tx];
    __syncthreads();
    #pragma unroll
    for (int i = 0; i < 4; i++) {
        float v = tile[tx][ty + i * 8];
        __half h = __float2half_rn(v);
        size_t o = (size_t)(n0 + ty + i * 8) * D_DIM + k0 + tx;
        g_wt_hi[o] = h;
        g_wt_lo[o] = __float2half_rn(v - __half2float(h));
    }
}

// w2 [e*FF+k][D] -> wt rows [e*D+d][ff], fp16 hi/lo (runs AFTER gemm1)
__global__ void transpose_w2_kernel(const float* __restrict__ w2) {
    __shared__ float tile[32][33];
    int c0 = blockIdx.x * 32, r0 = blockIdx.y * 32;
    int tx = threadIdx.x, ty = threadIdx.y;
    #pragma unroll
    for (int i = 0; i < 4; i++)
        tile[ty + i * 8][tx] = w2[(size_t)(r0 + ty + i * 8) * D_DIM + c0 + tx];
    __syncthreads();
    int e = r0 >> 11, kl = r0 & (FF_DIM - 1);
    #pragma unroll
    for (int i = 0; i < 4; i++) {
        float v = tile[tx][ty + i * 8];
        __half h = __float2half_rn(v);
        size_t o = (size_t)(e * D_DIM + c0 + ty + i * 8) * FF_DIM + kl + tx;
        g_wt_hi[o] = h;
        g_wt_lo[o] = __float2half_rn(v - __half2float(h));
    }
}

// ================= MMA GEMM core (fp16 asymmetric 2-term; cp.async 3-stage) =====
// D = A * (B_hi + B_lo): A single fp16 (x or h), B = fp16 split weights.
// IS_GEMM1: A = gather(g_x_h via rowtok) [K=D], epilogue gelu -> g_h_h (fp16)
// else:     A = g_h_h rows [K=FF],       epilogue weighted atomicAdd -> out
template <int KTOT, bool IS_GEMM1>
__global__ void __launch_bounds__(256, 1)
gemm_mma(float* __restrict__ out) {
    __shared__ __align__(16) char smem[NSTAGE * STAGE_SZ];   // 36 KB static

    const int N_TOTAL = IS_GEMM1 ? FF_DIM : D_DIM;

    int e = blockIdx.z;
    int n_e = g_cnt[e], base = g_base[e];
    int m0 = blockIdx.y * BM;
    if (m0 >= n_e) return;
    int n0 = blockIdx.x * BN;

    int tid = threadIdx.x, lane = tid & 31, wid = tid >> 5;
    uint32_t sb = smem_u32(smem);

    int crow = tid >> 1, cseg = tid & 1;
    const __half* pa;
    if (IS_GEMM1) {
        int arow_g = m0 + crow;
        int tok = (arow_g < n_e) ? g_rowtok[base + arow_g] : 0;
        pa = g_x_h + (size_t)tok * KTOT + cseg * 8;
    } else {
        pa = g_h_h + (size_t)(base + m0 + crow) * KTOT + cseg * 8;
    }
    size_t bo = ((size_t)e * N_TOTAL + n0 + crow) * KTOT + cseg * 8;
    const __half* pbh = g_wt_hi + bo;
    const __half* pbl = g_wt_lo + bo;
    uint32_t wdst = swz2(crow, cseg);

    const int NCH = KTOT / BK;

    auto issue = [&](int ch) {
        uint32_t d = sb + (ch % NSTAGE) * STAGE_SZ + wdst;
        int k0 = ch * BK;
        cpa16(d,              pa  + k0);
        cpa16(d + PART_B,     pbh + k0);
        cpa16(d + 2 * PART_B, pbl + k0);
    };

    issue(0); cp_commit();
    issue(1); cp_commit();
    issue(2); cp_commit();

    int warp_m = (wid & 1) * 64, warp_n = (wid >> 1) * 32;

    float acc[4][4][4];
    #pragma unroll
    for (int i = 0; i < 4; i++)
        #pragma unroll
        for (int j = 0; j < 4; j++)
            #pragma unroll
            for (int q = 0; q < 4; q++) acc[i][j][q] = 0.f;

    uint32_t aphys = swz2(warp_m + (lane & 15), lane >> 4);
    uint32_t bphys = swz2(warp_n + (lane & 7) + ((lane & 16) ? 8 : 0), (lane >> 3) & 1);

    for (int ch = 0; ch < NCH; ch++) {
        cp_wait2();
        __syncthreads();

        uint32_t st = sb + (ch % NSTAGE) * STAGE_SZ;
        uint32_t ah[4][4], bh[4][2], bl[4][2];

        #pragma unroll
        for (int mi = 0; mi < 4; mi++) ldsm4(ah[mi], st + aphys + mi * 512);
        #pragma unroll
        for (int ng = 0; ng < 2; ng++) {
            uint32_t r[4];
            ldsm4(r, st + PART_B + bphys + ng * 512);
            bh[ng * 2][0] = r[0]; bh[ng * 2][1] = r[1];
            bh[ng * 2 + 1][0] = r[2]; bh[ng * 2 + 1][1] = r[3];
        }
        // A*Bhi MMAs with Blo LDSMs interleaved into the first iterations
        #pragma unroll
        for (int mi = 0; mi < 4; mi++) {
            if (mi < 2) {
                uint32_t r[4];
                ldsm4(r, st + 2 * PART_B + bphys + mi * 512);
                bl[mi * 2][0] = r[0]; bl[mi * 2][1] = r[1];
                bl[mi * 2 + 1][0] = r[2]; bl[mi * 2 + 1][1] = r[3];
            }
            #pragma unroll
            for (int ni = 0; ni < 4; ni++) mma16816h(acc[mi][ni], ah[mi], bh[ni]);
        }
        #pragma unroll
        for (int mi = 0; mi < 4; mi++)
            #pragma unroll
            for (int ni = 0; ni < 4; ni++) mma16816h(acc[mi][ni], ah[mi], bl[ni]);

        __syncthreads();
        if (ch + 3 < NCH) issue(ch + 3);
        cp_commit();
    }

    // ---------------- epilogue ----------------
    #pragma unroll
    for (int mi = 0; mi < 4; mi++) {
        int gr0 = m0 + warp_m + mi * 16 + (lane >> 2);
        int gr1 = gr0 + 8;
        bool v0 = gr0 < n_e, v1 = gr1 < n_e;
        int tok0 = 0, tok1 = 0; float wgt0 = 0.f, wgt1 = 0.f;
        if (!IS_GEMM1) {
            if (v0) { tok0 = g_rowtok[base + gr0]; wgt0 = g_roww[base + gr0]; }
            if (v1) { tok1 = g_rowtok[base + gr1]; wgt1 = g_roww[base + gr1]; }
        }
        #pragma unroll
        for (int ni = 0; ni < 4; ni++) {
            int c_col = n0 + warp_n + ni * 8 + (lane & 3) * 2;
            float* a4 = acc[mi][ni];
            if (IS_GEMM1) {
                if (v0) {
                    size_t o = (size_t)(base + gr0) * FF_DIM + c_col;
                    *(uint32_t*)(g_h_h + o) = pack2hf(gelu_exact(a4[0]), gelu_exact(a4[1]));
                }
                if (v1) {
                    size_t o = (size_t)(base + gr1) * FF_DIM + c_col;
                    *(uint32_t*)(g_h_h + o) = pack2hf(gelu_exact(a4[2]), gelu_exact(a4[3]));
                }
            } else {
                if (v0) {
                    float* op = out + (size_t)tok0 * D_DIM + c_col;
                    atomicAdd(op,     wgt0 * a4[0]);
                    atomicAdd(op + 1, wgt0 * a4[1]);
                }
                if (v1) {
                    float* op = out + (size_t)tok1 * D_DIM + c_col;
                    atomicAdd(op,     wgt1 * a4[2]);
                    atomicAdd(op + 1, wgt1 * a4[3]);
                }
            }
        }
    }
}

// ---------------- finalize scalars ----------------
__global__ void finalize_kernel(float* __restrict__ out, int out_size) {
    if (threadIdx.x == 0) {
        float z = g_zsum / (float)T_TOK;
        float lb = 0.f;
        for (int e = 0; e < E_EXP; e++) {
            float f_i = (float)g_cnt[e] / (float)(T_TOK * TOPK);
            float p_i = g_psum[e] / (float)T_TOK;
            lb += f_i * p_i;
        }
        lb *= (float)E_EXP;
        out[out_size - 2] = z;
        out[out_size - 1] = lb;
    }
}

// ---------------- launch ----------------
extern "C" void kernel_launch(void* const* d_in, const int* in_sizes, int n_in,
                              void* d_out, int out_size) {
    const float* x  = (const float*)d_in[0];
    const float* rw = (const float*)d_in[1];
    const float* w1 = (const float*)d_in[2];
    const float* w2 = (const float*)d_in[3];
    float* out = (float*)d_out;

    init_kernel<<<1, 32>>>();
    router_kernel<<<T_TOK, 256>>>(x, rw);
    scan_kernel<<<1, 1>>>();
    place_kernel<<<(T_TOK + 255) / 256, 256>>>();

    convert_x_kernel<<<(T_TOK * D_DIM / 8) / 256, 256>>>(x);
    transpose_w1_kernel<<<dim3(EFF / 32, D_DIM / 32), dim3(32, 8)>>>(w1);

    // GEMM1 (consumes wt as w1t, writes g_h_h fp16)
    gemm_mma<D_DIM, true><<<dim3(FF_DIM / BN, T_TOK / BM, E_EXP), 256>>>(out);

    // reuse wt for w2t, then GEMM2 with fused weighted scatter into out
    transpose_w2_kernel<<<dim3(D_DIM / 32, EFF / 32), dim3(32, 8)>>>(w2);
    zero_out_kernel<<<(T_TOK * D_DIM / 4) / 256, 256>>>(out);
    gemm_mma<FF_DIM, false><<<dim3(D_DIM / BN, T_TOK / BM, E_EXP), 256>>>(out);

    finalize_kernel<<<1, 1>>>(out, out_size);
}

// round 16
// speedup vs baseline: 4.7788x; 1.5935x over previous
#include <cuda_runtime.h>
#include <cuda_fp16.h>
#include <math.h>
#include <stdint.h>

// ---------------- problem constants ----------------
#define T_TOK   8192
#define D_DIM   1024
#define E_EXP   8
#define TOPK    2
#define FF_DIM  2048
#define EFF     (E_EXP * FF_DIM)
#define NROWS   (T_TOK * TOPK)      // 16384
#define HPAD    128

// MMA GEMM tiling
#define BM 128
#define BN 128
#define BK 16
#define PART_B   4096                // 128 rows * 32 B of halves
#define STAGE_SZ (2 * PART_B)        // A | B = 8 KB
#define NSTAGE   3                   // 24 KB static shared

// ---------------- device scratch (~118 MB; no symbol crosses a launch) ----------------
__device__ __half g_x_h[(size_t)T_TOK * D_DIM];                 // 16.8 MB
__device__ __half g_wt[(size_t)EFF * D_DIM];                    // 33.5 MB (w1t, then w2t)
__device__ __half g_h_h[(size_t)(NROWS + HPAD) * FF_DIM];       // 67.6 MB
__device__ int   g_cnt[E_EXP];
__device__ int   g_base[E_EXP];
__device__ int   g_cursor[E_EXP];
__device__ int   g_rowtok[NROWS];
__device__ float g_roww[NROWS];
__device__ int   g_rowloc[NROWS];
__device__ int   g_sel[NROWS];
__device__ float g_wsel[NROWS];
__device__ float g_zsum;
__device__ float g_psum[E_EXP];

// ---------------- helpers ----------------
__device__ __forceinline__ uint32_t smem_u32(const void* p) {
    uint32_t a;
    asm("{ .reg .u64 t; cvta.to.shared.u64 t, %1; cvt.u32.u64 %0, t; }" : "=r"(a) : "l"(p));
    return a;
}
__device__ __forceinline__ void cpa16(uint32_t dst, const void* src) {
    asm volatile("cp.async.cg.shared.global [%0], [%1], 16;" :: "r"(dst), "l"(src) : "memory");
}
__device__ __forceinline__ void cp_commit() { asm volatile("cp.async.commit_group;" ::: "memory"); }
__device__ __forceinline__ void cp_wait2()  { asm volatile("cp.async.wait_group 2;" ::: "memory"); }

__device__ __forceinline__ void ldsm4(uint32_t* r, uint32_t addr) {
    asm volatile("ldmatrix.sync.aligned.m8n8.x4.shared.b16 {%0,%1,%2,%3}, [%4];"
                 : "=r"(r[0]), "=r"(r[1]), "=r"(r[2]), "=r"(r[3]) : "r"(addr));
}
__device__ __forceinline__ void mma16816h(float* c, const uint32_t* a, const uint32_t* b) {
    asm volatile("mma.sync.aligned.m16n8k16.row.col.f32.f16.f16.f32 "
                 "{%0,%1,%2,%3}, {%4,%5,%6,%7}, {%8,%9}, {%0,%1,%2,%3};"
                 : "+f"(c[0]), "+f"(c[1]), "+f"(c[2]), "+f"(c[3])
                 : "r"(a[0]), "r"(a[1]), "r"(a[2]), "r"(a[3]), "r"(b[0]), "r"(b[1]));
}
__device__ __forceinline__ float gelu_exact(float v) {
    return 0.5f * v * (1.0f + erff(v * 0.70710678118654752f));
}
__device__ __forceinline__ uint32_t swz2(int r, int s) {
    return (uint32_t)(r * 32 + (((s ^ r ^ (r >> 2)) & 1) << 4));
}
__device__ __forceinline__ uint32_t pack2hf(float a, float b) {
    __half2 h = __floats2half2_rn(a, b);
    return *(uint32_t*)&h;
}

// ---------------- init ----------------
__global__ void init_kernel() {
    int i = threadIdx.x;
    if (i < E_EXP) { g_cnt[i] = 0; g_psum[i] = 0.f; }
    if (i == 0)    { g_zsum = 0.f; }
}

__global__ void zero_out_kernel(float* __restrict__ out) {
    size_t i = ((size_t)blockIdx.x * blockDim.x + threadIdx.x) * 4;
    *(float4*)(out + i) = make_float4(0.f, 0.f, 0.f, 0.f);
}

// ---------------- router ----------------
__global__ void router_kernel(const float* __restrict__ x,
                              const float* __restrict__ rw) {
    __shared__ float sx[D_DIM];
    __shared__ float slog[E_EXP];
    int t = blockIdx.x;
    const float* xr = x + (size_t)t * D_DIM;
    for (int i = threadIdx.x; i < D_DIM; i += blockDim.x) sx[i] = xr[i];
    __syncthreads();

    int w = threadIdx.x >> 5, lane = threadIdx.x & 31;
    float acc = 0.f;
    const float* we = rw + w * D_DIM;
    for (int i = lane; i < D_DIM; i += 32) acc += sx[i] * we[i];
    #pragma unroll
    for (int o = 16; o; o >>= 1) acc += __shfl_xor_sync(0xffffffffu, acc, o);
    if (lane == 0) slog[w] = acc;
    __syncthreads();

    if (threadIdx.x == 0) {
        float l[E_EXP], p[E_EXP];
        float m = -1e30f;
        #pragma unroll
        for (int e = 0; e < E_EXP; e++) { l[e] = slog[e]; m = fmaxf(m, l[e]); }
        float s = 0.f;
        #pragma unroll
        for (int e = 0; e < E_EXP; e++) { p[e] = expf(l[e] - m); s += p[e]; }
        float inv_s = 1.f / s;
        #pragma unroll
        for (int e = 0; e < E_EXP; e++) p[e] *= inv_s;
        float lse = m + logf(s);
        atomicAdd(&g_zsum, lse * lse);
        #pragma unroll
        for (int e = 0; e < E_EXP; e++) atomicAdd(&g_psum[e], p[e]);

        int i0 = 0; float p0 = p[0];
        #pragma unroll
        for (int e = 1; e < E_EXP; e++) if (p[e] > p0) { p0 = p[e]; i0 = e; }
        int i1 = -1; float p1 = -1.f;
        #pragma unroll
        for (int e = 0; e < E_EXP; e++) {
            if (e == i0) continue;
            if (p[e] > p1) { p1 = p[e]; i1 = e; }
        }
        float invn = 1.f / (p0 + p1);
        g_sel[2 * t + 0] = i0; g_wsel[2 * t + 0] = p0 * invn;
        g_sel[2 * t + 1] = i1; g_wsel[2 * t + 1] = p1 * invn;
        atomicAdd(&g_cnt[i0], 1);
        atomicAdd(&g_cnt[i1], 1);
    }
}

__global__ void scan_kernel() {
    if (threadIdx.x == 0) {
        int o = 0;
        for (int e = 0; e < E_EXP; e++) { g_base[e] = o; g_cursor[e] = o; o += g_cnt[e]; }
    }
}

__global__ void place_kernel() {
    int t = blockIdx.x * blockDim.x + threadIdx.x;
    if (t >= T_TOK) return;
    #pragma unroll
    for (int k = 0; k < TOPK; k++) {
        int e = g_sel[2 * t + k];
        int pos = atomicAdd(&g_cursor[e], 1);
        g_rowtok[pos] = t;
        g_roww[pos] = g_wsel[2 * t + k];
        g_rowloc[2 * t + k] = pos;
    }
}

// ---------------- pre-conversions ----------------
__global__ void convert_x_kernel(const float* __restrict__ x) {
    size_t i = ((size_t)blockIdx.x * blockDim.x + threadIdx.x) * 8;
    float4 v0 = *(const float4*)(x + i);
    float4 v1 = *(const float4*)(x + i + 4);
    uint4 p;
    p.x = pack2hf(v0.x, v0.y);
    p.y = pack2hf(v0.z, v0.w);
    p.z = pack2hf(v1.x, v1.y);
    p.w = pack2hf(v1.z, v1.w);
    *(uint4*)(g_x_h + i) = p;
}

// w1 [D][EFF] -> wt rows [e*FF+ff][d], single fp16
__global__ void transpose_w1_kernel(const float* __restrict__ w1) {
    __shared__ float tile[32][33];
    int n0 = blockIdx.x * 32, k0 = blockIdx.y * 32;
    int tx = threadIdx.x, ty = threadIdx.y;
    #pragma unroll
    for (int i = 0; i < 4; i++)
        tile[ty + i * 8][tx] = w1[(size_t)(k0 + ty + i * 8) * EFF + n0 + tx];
    __syncthreads();
    #pragma unroll
    for (int i = 0; i < 4; i++)
        g_wt[(size_t)(n0 + ty + i * 8) * D_DIM + k0 + tx] = __float2half_rn(tile[tx][ty + i * 8]);
}

// w2 [e*FF+k][D] -> wt rows [e*D+d][ff], single fp16 (runs AFTER gemm1)
__global__ void transpose_w2_kernel(const float* __restrict__ w2) {
    __shared__ float tile[32][33];
    int c0 = blockIdx.x * 32, r0 = blockIdx.y * 32;
    int tx = threadIdx.x, ty = threadIdx.y;
    #pragma unroll
    for (int i = 0; i < 4; i++)
        tile[ty + i * 8][tx] = w2[(size_t)(r0 + ty + i * 8) * D_DIM + c0 + tx];
    __syncthreads();
    int e = r0 >> 11, kl = r0 & (FF_DIM - 1);
    #pragma unroll
    for (int i = 0; i < 4; i++)
        g_wt[(size_t)(e * D_DIM + c0 + ty + i * 8) * FF_DIM + kl + tx] = __float2half_rn(tile[tx][ty + i * 8]);
}

// ================= MMA GEMM core (pure fp16 1-term; cp.async 3-stage) ===========
// IS_GEMM1: A = gather(g_x_h via rowtok) [K=D], epilogue gelu -> g_h_h (fp16)
// else:     A = g_h_h rows [K=FF],       epilogue weighted atomicAdd -> out
template <int KTOT, bool IS_GEMM1>
__global__ void __launch_bounds__(256, 1)
gemm_mma(float* __restrict__ out) {
    __shared__ __align__(16) char smem[NSTAGE * STAGE_SZ];   // 24 KB static

    const int N_TOTAL = IS_GEMM1 ? FF_DIM : D_DIM;

    int e = blockIdx.z;
    int n_e = g_cnt[e], base = g_base[e];
    int m0 = blockIdx.y * BM;
    if (m0 >= n_e) return;
    int n0 = blockIdx.x * BN;

    int tid = threadIdx.x, lane = tid & 31, wid = tid >> 5;
    uint32_t sb = smem_u32(smem);

    int crow = tid >> 1, cseg = tid & 1;
    const __half* pa;
    if (IS_GEMM1) {
        int arow_g = m0 + crow;
        int tok = (arow_g < n_e) ? g_rowtok[base + arow_g] : 0;
        pa = g_x_h + (size_t)tok * KTOT + cseg * 8;
    } else {
        pa = g_h_h + (size_t)(base + m0 + crow) * KTOT + cseg * 8;
    }
    const __half* pb = g_wt + ((size_t)e * N_TOTAL + n0 + crow) * KTOT + cseg * 8;
    uint32_t wdst = swz2(crow, cseg);

    const int NCH = KTOT / BK;

    auto issue = [&](int ch) {
        uint32_t d = sb + (ch % NSTAGE) * STAGE_SZ + wdst;
        int k0 = ch * BK;
        cpa16(d,          pa + k0);
        cpa16(d + PART_B, pb + k0);
    };

    issue(0); cp_commit();
    issue(1); cp_commit();
    issue(2); cp_commit();

    int warp_m = (wid & 1) * 64, warp_n = (wid >> 1) * 32;

    float acc[4][4][4];
    #pragma unroll
    for (int i = 0; i < 4; i++)
        #pragma unroll
        for (int j = 0; j < 4; j++)
            #pragma unroll
            for (int q = 0; q < 4; q++) acc[i][j][q] = 0.f;

    uint32_t aphys = swz2(warp_m + (lane & 15), lane >> 4);
    uint32_t bphys = swz2(warp_n + (lane & 7) + ((lane & 16) ? 8 : 0), (lane >> 3) & 1);

    for (int ch = 0; ch < NCH; ch++) {
        cp_wait2();
        __syncthreads();

        uint32_t st = sb + (ch % NSTAGE) * STAGE_SZ;
        uint32_t ah[4][4], bfr[4][2];

        #pragma unroll
        for (int mi = 0; mi < 4; mi++) ldsm4(ah[mi], st + aphys + mi * 512);
        #pragma unroll
        for (int ng = 0; ng < 2; ng++) {
            uint32_t r[4];
            ldsm4(r, st + PART_B + bphys + ng * 512);
            bfr[ng * 2][0] = r[0]; bfr[ng * 2][1] = r[1];
            bfr[ng * 2 + 1][0] = r[2]; bfr[ng * 2 + 1][1] = r[3];
        }
        #pragma unroll
        for (int mi = 0; mi < 4; mi++)
            #pragma unroll
            for (int ni = 0; ni < 4; ni++) mma16816h(acc[mi][ni], ah[mi], bfr[ni]);

        __syncthreads();
        if (ch + 3 < NCH) issue(ch + 3);
        cp_commit();
    }

    // ---------------- epilogue ----------------
    #pragma unroll
    for (int mi = 0; mi < 4; mi++) {
        int gr0 = m0 + warp_m + mi * 16 + (lane >> 2);
        int gr1 = gr0 + 8;
        bool v0 = gr0 < n_e, v1 = gr1 < n_e;
        int tok0 = 0, tok1 = 0; float wgt0 = 0.f, wgt1 = 0.f;
        if (!IS_GEMM1) {
            if (v0) { tok0 = g_rowtok[base + gr0]; wgt0 = g_roww[base + gr0]; }
            if (v1) { tok1 = g_rowtok[base + gr1]; wgt1 = g_roww[base + gr1]; }
        }
        #pragma unroll
        for (int ni = 0; ni < 4; ni++) {
            int c_col = n0 + warp_n + ni * 8 + (lane & 3) * 2;
            float* a4 = acc[mi][ni];
            if (IS_GEMM1) {
                if (v0) {
                    size_t o = (size_t)(base + gr0) * FF_DIM + c_col;
                    *(uint32_t*)(g_h_h + o) = pack2hf(gelu_exact(a4[0]), gelu_exact(a4[1]));
                }
                if (v1) {
                    size_t o = (size_t)(base + gr1) * FF_DIM + c_col;
                    *(uint32_t*)(g_h_h + o) = pack2hf(gelu_exact(a4[2]), gelu_exact(a4[3]));
                }
            } else {
                if (v0) {
                    float* op = out + (size_t)tok0 * D_DIM + c_col;
                    atomicAdd(op,     wgt0 * a4[0]);
                    atomicAdd(op + 1, wgt0 * a4[1]);
                }
                if (v1) {
                    float* op = out + (size_t)tok1 * D_DIM + c_col;
                    atomicAdd(op,     wgt1 * a4[2]);
                    atomicAdd(op + 1, wgt1 * a4[3]);
                }
            }
        }
    }
}

// ---------------- finalize scalars ----------------
__global__ void finalize_kernel(float* __restrict__ out, int out_size) {
    if (threadIdx.x == 0) {
        float z = g_zsum / (float)T_TOK;
        float lb = 0.f;
        for (int e = 0; e < E_EXP; e++) {
            float f_i = (float)g_cnt[e] / (float)(T_TOK * TOPK);
            float p_i = g_psum[e] / (float)T_TOK;
            lb += f_i * p_i;
        }
        lb *= (float)E_EXP;
        out[out_size - 2] = z;
        out[out_size - 1] = lb;
    }
}

// ---------------- launch ----------------
extern "C" void kernel_launch(void* const* d_in, const int* in_sizes, int n_in,
                              void* d_out, int out_size) {
    const float* x  = (const float*)d_in[0];
    const float* rw = (const float*)d_in[1];
    const float* w1 = (const float*)d_in[2];
    const float* w2 = (const float*)d_in[3];
    float* out = (float*)d_out;

    init_kernel<<<1, 32>>>();
    router_kernel<<<T_TOK, 256>>>(x, rw);
    scan_kernel<<<1, 1>>>();
    place_kernel<<<(T_TOK + 255) / 256, 256>>>();

    convert_x_kernel<<<(T_TOK * D_DIM / 8) / 256, 256>>>(x);
    transpose_w1_kernel<<<dim3(EFF / 32, D_DIM / 32), dim3(32, 8)>>>(w1);

    // GEMM1 (consumes wt as w1t, writes g_h_h fp16)
    gemm_mma<D_DIM, true><<<dim3(FF_DIM / BN, T_TOK / BM, E_EXP), 256>>>(out);

    // reuse wt for w2t, then GEMM2 with fused weighted scatter into out
    transpose_w2_kernel<<<dim3(D_DIM / 32, EFF / 32), dim3(32, 8)>>>(w2);
    zero_out_kernel<<<(T_TOK * D_DIM / 4) / 256, 256>>>(out);
    gemm_mma<FF_DIM, false><<<dim3(D_DIM / BN, T_TOK / BM, E_EXP), 256>>>(out);

    finalize_kernel<<<1, 1>>>(out, out_size);
}